// round 1
// baseline (speedup 1.0000x reference)
#include <cuda_runtime.h>

#define HIDDEN 192
#define MAXDEG 32
#define NTHREADS 96

// ---------- packed fp32x2 helpers (Blackwell sm_103a) ----------
__device__ __forceinline__ void fma2(unsigned long long &d, unsigned long long a,
                                     unsigned long long b) {
    asm("fma.rn.f32x2 %0, %1, %2, %0;" : "+l"(d) : "l"(a), "l"(b));
}
__device__ __forceinline__ unsigned long long dup2(float x) {
    unsigned long long r;
    asm("mov.b64 %0, {%1, %1};" : "=l"(r) : "f"(x));
    return r;
}
__device__ __forceinline__ float2 unpack2(unsigned long long v) {
    float2 f;
    asm("mov.b64 {%0, %1}, %2;" : "=f"(f.x), "=f"(f.y) : "l"(v));
    return f;
}

// ---------- math helpers ----------
// sin/cos on [0,1] via Taylor — avoids MUFU (which would bottleneck at ~340us)
__device__ __forceinline__ float sin_poly(float x) {
    float x2 = x * x;
    float p = -1.98412698e-4f;              // -1/5040
    p = fmaf(p, x2, 8.33333333e-3f);        //  1/120
    p = fmaf(p, x2, -1.66666667e-1f);       // -1/6
    return fmaf(x * x2, p, x);              // x + x^3*p
}
__device__ __forceinline__ float cos_poly(float x) {
    float x2 = x * x;
    float p = 2.48015873e-5f;               //  1/40320
    p = fmaf(p, x2, -1.38888889e-3f);       // -1/720
    p = fmaf(p, x2, 4.16666667e-2f);        //  1/24
    p = fmaf(p, x2, -0.5f);
    return fmaf(p, x2, 1.0f);
}
__device__ __forceinline__ float gelu_exact(float x) {
    return 0.5f * x * (1.0f + erff(x * 0.7071067811865476f));
}

// node embedding channel c: feat·Win[:,c] + b_in[c] + sincos(pos)
__device__ __forceinline__ float embed_channel(int c, float f0, float f1, float f2,
                                               const float* pp, const float* sWin,
                                               const float* sBin, const float* sOmega) {
    float v = sBin[c];
    v = fmaf(f0, sWin[c], v);
    v = fmaf(f1, sWin[HIDDEN + c], v);
    v = fmaf(f2, sWin[2 * HIDDEN + c], v);
    int axis = c >> 6;        // HIDDEN/NDIM = 64 channels per axis
    int j = c & 63;
    float ang = pp[axis] * sOmega[j & 31];
    float e = (j < 32) ? sin_poly(ang) : cos_poly(ang);
    return v + e;
}

__global__ void __launch_bounds__(NTHREADS)
supernode_pool_kernel(const float* __restrict__ feat, const float* __restrict__ pos,
                      const int* __restrict__ src_idx, const int* __restrict__ dst_idx,
                      const float* __restrict__ Win, const float* __restrict__ bin,
                      const float* __restrict__ W1, const float* __restrict__ b1,
                      const float* __restrict__ W2, const float* __restrict__ b2,
                      float* __restrict__ out) {
    __shared__ __align__(16) float sXs[HIDDEN][36];   // Xsrc transposed [k][m], padded
    __shared__ float sWin[3 * HIDDEN];
    __shared__ float sBin[HIDDEN];
    __shared__ float sOmega[32];
    __shared__ float sXd[HIDDEN];                      // dst node embedding
    __shared__ float sDst[HIDDEN];                     // b1 + x_dst @ W1_bot
    __shared__ float sRed[4][HIDDEN];                  // cross-row reduction
    __shared__ float sHm[HIDDEN];                      // mean(h)

    const int s = blockIdx.x;
    const int tid = threadIdx.x;

    // ---- stage constants ----
    for (int i = tid; i < 3 * HIDDEN; i += NTHREADS) sWin[i] = Win[i];
    for (int i = tid; i < HIDDEN; i += NTHREADS) sBin[i] = bin[i];
    if (tid < 32) sOmega[tid] = exp2f(-(float)tid * 0.4152410118609203f); // 10000^(-i/32)
    __syncthreads();

    // ---- dst embedding (shared by all 32 edges) ----
    {
        int dn = dst_idx[s * MAXDEG];
        float f0 = feat[dn * 3 + 0], f1 = feat[dn * 3 + 1], f2 = feat[dn * 3 + 2];
        float pp[3] = {pos[dn * 3 + 0], pos[dn * 3 + 1], pos[dn * 3 + 2]};
        int c = tid * 2;
        sXd[c] = embed_channel(c, f0, f1, f2, pp, sWin, sBin, sOmega);
        sXd[c + 1] = embed_channel(c + 1, f0, f1, f2, pp, sWin, sBin, sOmega);
    }

    // ---- src embeddings -> sXs[k][m] (warp lane == edge: conflict-free writes) ----
    {
        int m = tid & 31;
        int g = tid >> 5;  // channel group 0..2 (64 channels each)
        int sn = src_idx[s * MAXDEG + m];
        float f0 = feat[sn * 3 + 0], f1 = feat[sn * 3 + 1], f2 = feat[sn * 3 + 2];
        float pp[3] = {pos[sn * 3 + 0], pos[sn * 3 + 1], pos[sn * 3 + 2]};
        int cbase = g * 64;
#pragma unroll 4
        for (int i = 0; i < 64; ++i) {
            int c = cbase + i;
            sXs[c][m] = embed_channel(c, f0, f1, f2, pp, sWin, sBin, sOmega);
        }
    }
    __syncthreads();

    // ---- dst partial: sDst[n] = b1[n] + sum_k xd[k]*W1[192+k][n] ----
    {
        int n = tid * 2;
        float a0 = b1[n], a1 = b1[n + 1];
        const float* Wb = W1 + HIDDEN * HIDDEN;  // rows 192..383
#pragma unroll 4
        for (int k = 0; k < HIDDEN; ++k) {
            float xv = sXd[k];
            float2 w = *reinterpret_cast<const float2*>(&Wb[k * HIDDEN + n]);
            a0 = fmaf(xv, w.x, a0);
            a1 = fmaf(xv, w.y, a1);
        }
        sDst[n] = a0;
        sDst[n + 1] = a1;
    }
    __syncthreads();

    // ---- main GEMM: acc[32m][192n] = Xsrc @ W1_top, 8x8 thread tiles ----
    const int cc = tid % 24;   // 24 n-columns * 8 = 192
    const int r = tid / 24;    // 4 m-rows * 8 = 32
    const int n0 = cc * 8;
    const int m0 = r * 8;

    unsigned long long acc[8][4];  // [m][n-pair] packed f32x2
#pragma unroll
    for (int m = 0; m < 8; ++m)
#pragma unroll
        for (int np = 0; np < 4; ++np) acc[m][np] = 0ULL;

#pragma unroll 2
    for (int k = 0; k < HIDDEN; ++k) {
        float4 av0 = *reinterpret_cast<const float4*>(&sXs[k][m0]);
        float4 av1 = *reinterpret_cast<const float4*>(&sXs[k][m0 + 4]);
        ulonglong2 bv0 = *reinterpret_cast<const ulonglong2*>(&W1[k * HIDDEN + n0]);
        ulonglong2 bv1 = *reinterpret_cast<const ulonglong2*>(&W1[k * HIDDEN + n0 + 4]);
        unsigned long long bb[4] = {bv0.x, bv0.y, bv1.x, bv1.y};
        unsigned long long a2[8];
        a2[0] = dup2(av0.x); a2[1] = dup2(av0.y); a2[2] = dup2(av0.z); a2[3] = dup2(av0.w);
        a2[4] = dup2(av1.x); a2[5] = dup2(av1.y); a2[6] = dup2(av1.z); a2[7] = dup2(av1.w);
#pragma unroll
        for (int m = 0; m < 8; ++m) {
            fma2(acc[m][0], a2[m], bb[0]);
            fma2(acc[m][1], a2[m], bb[1]);
            fma2(acc[m][2], a2[m], bb[2]);
            fma2(acc[m][3], a2[m], bb[3]);
        }
    }

    // ---- epilogue: + dstpart, GELU, column-sum over m ----
    float colsum[8];
#pragma unroll
    for (int j = 0; j < 8; ++j) colsum[j] = 0.0f;
#pragma unroll
    for (int m = 0; m < 8; ++m) {
#pragma unroll
        for (int np = 0; np < 4; ++np) {
            float2 v = unpack2(acc[m][np]);
            float h0 = gelu_exact(v.x + sDst[n0 + np * 2]);
            float h1 = gelu_exact(v.y + sDst[n0 + np * 2 + 1]);
            colsum[np * 2] += h0;
            colsum[np * 2 + 1] += h1;
        }
    }
#pragma unroll
    for (int j = 0; j < 8; ++j) sRed[r][n0 + j] = colsum[j];
    __syncthreads();

    // reduce 4 row-groups, divide by degree -> mean(h)
    {
        int n = tid * 2;
        sHm[n] = (sRed[0][n] + sRed[1][n] + sRed[2][n] + sRed[3][n]) * (1.0f / 32.0f);
        sHm[n + 1] =
            (sRed[0][n + 1] + sRed[1][n + 1] + sRed[2][n + 1] + sRed[3][n + 1]) * (1.0f / 32.0f);
    }
    __syncthreads();

    // ---- second GEMM (tiny): out = mean(h) @ W2 + b2 ----
    {
        int n = tid * 2;
        float a0 = b2[n], a1 = b2[n + 1];
#pragma unroll 4
        for (int k = 0; k < HIDDEN; ++k) {
            float hv = sHm[k];
            float2 w = *reinterpret_cast<const float2*>(&W2[k * HIDDEN + n]);
            a0 = fmaf(hv, w.x, a0);
            a1 = fmaf(hv, w.y, a1);
        }
        out[s * HIDDEN + n] = a0;
        out[s * HIDDEN + n + 1] = a1;
    }
}

extern "C" void kernel_launch(void* const* d_in, const int* in_sizes, int n_in,
                              void* d_out, int out_size) {
    const float* feat = (const float*)d_in[0];
    const float* pos = (const float*)d_in[1];
    const int* src_idx = (const int*)d_in[2];
    const int* dst_idx = (const int*)d_in[3];
    const float* Win = (const float*)d_in[4];
    const float* bin = (const float*)d_in[5];
    const float* W1 = (const float*)d_in[6];
    const float* b1 = (const float*)d_in[7];
    const float* W2 = (const float*)d_in[8];
    const float* b2 = (const float*)d_in[9];
    float* out = (float*)d_out;

    int E = in_sizes[2];       // src_idx element count
    int S = E / MAXDEG;        // 8192 supernodes

    supernode_pool_kernel<<<S, NTHREADS>>>(feat, pos, src_idx, dst_idx, Win, bin, W1, b1,
                                           W2, b2, out);
}

// round 5
// speedup vs baseline: 1.8512x; 1.8512x over previous
#include <cuda_runtime.h>
#include <cuda_bf16.h>
#include <cstdint>

#define HIDDEN 192
#define MAXDEG 32
#define MAX_S 8192

// scratch (device globals: allocation-free). 16B-aligned for vector ld/st.
__device__ __align__(16) float g_dstpart[MAX_S * HIDDEN];        // b1 + x_dst @ W1_bot
__device__ __align__(16) float g_pooled[MAX_S * HIDDEN];         // mean(gelu(...))
__device__ __align__(16) __nv_bfloat16 g_W1Thi[HIDDEN * HIDDEN]; // W1_top^T hi [n][k]
__device__ __align__(16) __nv_bfloat16 g_W1Tlo[HIDDEN * HIDDEN]; // W1_top^T lo [n][k]

// ---------------- helpers ----------------
__device__ __forceinline__ void fma2(unsigned long long &d, unsigned long long a,
                                     unsigned long long b) {
    asm("fma.rn.f32x2 %0, %1, %2, %0;" : "+l"(d) : "l"(a), "l"(b));
}
__device__ __forceinline__ unsigned long long dup2(float x) {
    unsigned long long r;
    asm("mov.b64 %0, {%1, %1};" : "=l"(r) : "f"(x));
    return r;
}
__device__ __forceinline__ float2 unpack2(unsigned long long v) {
    float2 f;
    asm("mov.b64 {%0, %1}, %2;" : "=f"(f.x), "=f"(f.y) : "l"(v));
    return f;
}
__device__ __forceinline__ float sin_poly(float x) {
    float x2 = x * x;
    float p = -1.98412698e-4f;
    p = fmaf(p, x2, 8.33333333e-3f);
    p = fmaf(p, x2, -1.66666667e-1f);
    return fmaf(x * x2, p, x);
}
__device__ __forceinline__ float cos_poly(float x) {
    float x2 = x * x;
    float p = 2.48015873e-5f;
    p = fmaf(p, x2, -1.38888889e-3f);
    p = fmaf(p, x2, 4.16666667e-2f);
    p = fmaf(p, x2, -0.5f);
    return fmaf(p, x2, 1.0f);
}
__device__ __forceinline__ float gelu_exact(float x) {
    return 0.5f * x * (1.0f + erff(x * 0.7071067811865476f));
}
__device__ __forceinline__ float embed_channel(int c, float f0, float f1, float f2,
                                               const float* pp, const float* sWin,
                                               const float* sBin, const float* sOmega) {
    float v = sBin[c];
    v = fmaf(f0, sWin[c], v);
    v = fmaf(f1, sWin[HIDDEN + c], v);
    v = fmaf(f2, sWin[2 * HIDDEN + c], v);
    int axis = c >> 6;
    int j = c & 63;
    float ang = pp[axis] * sOmega[j & 31];
    float e = (j < 32) ? sin_poly(ang) : cos_poly(ang);
    return v + e;
}
__device__ __forceinline__ void mma_bf16(float* c, uint32_t a0, uint32_t a1, uint32_t a2,
                                         uint32_t a3, uint32_t b0, uint32_t b1) {
    asm volatile(
        "mma.sync.aligned.m16n8k16.row.col.f32.bf16.bf16.f32 "
        "{%0,%1,%2,%3}, {%4,%5,%6,%7}, {%8,%9}, {%0,%1,%2,%3};"
        : "+f"(c[0]), "+f"(c[1]), "+f"(c[2]), "+f"(c[3])
        : "r"(a0), "r"(a1), "r"(a2), "r"(a3), "r"(b0), "r"(b1));
}
__device__ __forceinline__ uint32_t pack_bf16(float v0, float v1) {
    __nv_bfloat162 t;
    t.x = __float2bfloat16(v0);
    t.y = __float2bfloat16(v1);
    return *reinterpret_cast<uint32_t*>(&t);
}

// ============================================================
// Kernel P: split W1_top into bf16 hi/lo, transposed to [n][k]
// ============================================================
__global__ void __launch_bounds__(256)
w1_split_kernel(const float* __restrict__ W1) {
    int i = blockIdx.x * 256 + threadIdx.x;
    if (i >= HIDDEN * HIDDEN) return;
    int k = i / HIDDEN, n = i % HIDDEN;
    float w = W1[k * HIDDEN + n];
    __nv_bfloat16 hi = __float2bfloat16(w);
    float lo = w - __bfloat162float(hi);
    g_W1Thi[n * HIDDEN + k] = hi;
    g_W1Tlo[n * HIDDEN + k] = __float2bfloat16(lo);
}

// ============================================================
// Kernel A: dst partial (32 supernodes / 128 threads, FFMA2)
// ============================================================
__global__ void __launch_bounds__(128)
dst_partial_kernel(const float* __restrict__ feat, const float* __restrict__ pos,
                   const int* __restrict__ dst_idx, const float* __restrict__ Win,
                   const float* __restrict__ bin, const float* __restrict__ W1,
                   const float* __restrict__ b1) {
    __shared__ float sX[32 * HIDDEN];
    __shared__ float sWin[3 * HIDDEN], sBin[HIDDEN], sOmega[32];
    const int tid = threadIdx.x;
    const int s0 = blockIdx.x * 32;

    for (int i = tid; i < 3 * HIDDEN; i += 128) sWin[i] = Win[i];
    for (int i = tid; i < HIDDEN; i += 128) sBin[i] = bin[i];
    if (tid < 32) sOmega[tid] = exp2f(-(float)tid * 0.4152410118609203f);
    __syncthreads();

    for (int i = tid; i < 32 * HIDDEN; i += 128) {
        int r = i / HIDDEN, c = i % HIDDEN;
        int node = dst_idx[(s0 + r) * MAXDEG];
        float f0 = feat[node * 3], f1 = feat[node * 3 + 1], f2 = feat[node * 3 + 2];
        float pp[3] = {pos[node * 3], pos[node * 3 + 1], pos[node * 3 + 2]};
        sX[i] = embed_channel(c, f0, f1, f2, pp, sWin, sBin, sOmega);
    }
    __syncthreads();

    const float* Wb = W1 + HIDDEN * HIDDEN;
    const int r0 = (tid >> 5) * 8;
    const int n0 = (tid & 31) * 6;
    unsigned long long acc[8][3];
#pragma unroll
    for (int i = 0; i < 8; ++i)
#pragma unroll
        for (int j = 0; j < 3; ++j) acc[i][j] = 0ULL;
#pragma unroll 2
    for (int k = 0; k < HIDDEN; ++k) {
        const unsigned long long* bp = (const unsigned long long*)&Wb[k * HIDDEN + n0];
        unsigned long long b0 = bp[0], bq = bp[1], b2_ = bp[2];
#pragma unroll
        for (int i = 0; i < 8; ++i) {
            unsigned long long a = dup2(sX[(r0 + i) * HIDDEN + k]);
            fma2(acc[i][0], a, b0);
            fma2(acc[i][1], a, bq);
            fma2(acc[i][2], a, b2_);
        }
    }
#pragma unroll
    for (int i = 0; i < 8; ++i) {
        float* o = &g_dstpart[(s0 + r0 + i) * HIDDEN + n0];
#pragma unroll
        for (int j = 0; j < 3; ++j) {
            float2 v = unpack2(acc[i][j]);
            o[j * 2] = v.x + b1[n0 + j * 2];
            o[j * 2 + 1] = v.y + b1[n0 + j * 2 + 1];
        }
    }
}

// ============================================================
// Kernel B: mma.sync bf16 3-term edge GEMM + GELU + pooled mean
// CTA = 2 supernodes (M=64), 256 threads, 8 warps
// warp (wm = w&3, wn = w>>2): 16m x 96n = 12 m16n8 atoms
// ============================================================
#define STRIDE_A 72        // 32 bf16 (64B) + 8B pad
#define STRIDE_B 80        // 32 bf16 (64B) + 16B pad (rows stay 16B aligned)

__global__ void __launch_bounds__(256, 2)
snp_mma_kernel(const float* __restrict__ feat, const float* __restrict__ pos,
               const int* __restrict__ src_idx, const float* __restrict__ Win,
               const float* __restrict__ bin) {
    __shared__ __align__(16) unsigned char sAhi[64 * STRIDE_A];
    __shared__ __align__(16) unsigned char sAlo[64 * STRIDE_A];
    __shared__ __align__(16) unsigned char sBhi[HIDDEN * STRIDE_B];
    __shared__ __align__(16) unsigned char sBlo[HIDDEN * STRIDE_B];
    __shared__ float sWin[3 * HIDDEN], sBin[HIDDEN], sOmega[32];
    __shared__ float sDst[2 * HIDDEN];
    __shared__ float sCol[4][HIDDEN];

    const int b = blockIdx.x;
    const int tid = threadIdx.x;
    const int lane = tid & 31;
    const int w = tid >> 5;
    const int wm = w & 3, wn = w >> 2;
    const int g = lane >> 2, tg = lane & 3;

    for (int i = tid; i < 3 * HIDDEN; i += 256) sWin[i] = Win[i];
    for (int i = tid; i < HIDDEN; i += 256) sBin[i] = bin[i];
    for (int i = tid; i < 2 * HIDDEN; i += 256) sDst[i] = g_dstpart[b * 2 * HIDDEN + i];
    if (tid < 32) sOmega[tid] = exp2f(-(float)tid * 0.4152410118609203f);

    // per-thread edge state for A producers (threads 0..127)
    float f0 = 0.f, f1 = 0.f, f2 = 0.f, pp[3] = {0.f, 0.f, 0.f};
    const int m = tid & 63;
    const int cg = (tid >> 6) & 1;
    if (tid < 128) {
        int node = src_idx[b * 64 + m];
        f0 = feat[node * 3]; f1 = feat[node * 3 + 1]; f2 = feat[node * 3 + 2];
        pp[0] = pos[node * 3]; pp[1] = pos[node * 3 + 1]; pp[2] = pos[node * 3 + 2];
    }
    __syncthreads();

    float acc[12][4];
#pragma unroll
    for (int i = 0; i < 12; ++i)
#pragma unroll
        for (int j = 0; j < 4; ++j) acc[i][j] = 0.0f;

    const uint32_t aoff = (uint32_t)(wm * 16 + g) * STRIDE_A + tg * 4;
    const uint32_t boff = (uint32_t)(wn * 96 + g) * STRIDE_B + tg * 4;

    for (int ch = 0; ch < 6; ++ch) {
        // ---- produce ----
        if (tid < 128) {
            const int jb = cg * 16;
#pragma unroll
            for (int j = 0; j < 16; j += 2) {
                int c0 = ch * 32 + jb + j;
                float v0 = embed_channel(c0, f0, f1, f2, pp, sWin, sBin, sOmega);
                float v1 = embed_channel(c0 + 1, f0, f1, f2, pp, sWin, sBin, sOmega);
                __nv_bfloat16 h0 = __float2bfloat16(v0);
                __nv_bfloat16 h1 = __float2bfloat16(v1);
                float l0 = v0 - __bfloat162float(h0);
                float l1 = v1 - __bfloat162float(h1);
                __nv_bfloat162 hp; hp.x = h0; hp.y = h1;
                uint32_t hu = *reinterpret_cast<uint32_t*>(&hp);
                uint32_t lu = pack_bf16(l0, l1);
                *(uint32_t*)(sAhi + m * STRIDE_A + (jb + j) * 2) = hu;
                *(uint32_t*)(sAlo + m * STRIDE_A + (jb + j) * 2) = lu;
            }
        } else {
            // B chunk: 16B register copies. i = 0..5 -> hi half, 6..11 -> lo half.
            // id = t2 + 128*(i%6) covers [0, 768) exactly: n = id/4, seg = id%4.
            const int t2 = tid - 128;
#pragma unroll
            for (int i = 0; i < 12; ++i) {
                int isLo = i >= 6;
                int id = t2 + 128 * (isLo ? (i - 6) : i);   // 0..767
                int n = id >> 2, seg = id & 3;
                const __nv_bfloat16* src =
                    (isLo ? g_W1Tlo : g_W1Thi) + n * HIDDEN + ch * 32 + seg * 8;
                unsigned char* dst = (isLo ? sBlo : sBhi) + n * STRIDE_B + seg * 16;
                uint4 v = *reinterpret_cast<const uint4*>(src);
                *reinterpret_cast<uint4*>(dst) = v;
            }
        }
        __syncthreads();

        // ---- consume: 2 k-steps of 16 ----
#pragma unroll
        for (int ks = 0; ks < 2; ++ks) {
            const uint32_t ao = aoff + ks * 32;
            uint32_t ah0 = *(const uint32_t*)(sAhi + ao);
            uint32_t ah1 = *(const uint32_t*)(sAhi + ao + 8 * STRIDE_A);
            uint32_t ah2 = *(const uint32_t*)(sAhi + ao + 16);
            uint32_t ah3 = *(const uint32_t*)(sAhi + ao + 8 * STRIDE_A + 16);
            uint32_t al0 = *(const uint32_t*)(sAlo + ao);
            uint32_t al1 = *(const uint32_t*)(sAlo + ao + 8 * STRIDE_A);
            uint32_t al2 = *(const uint32_t*)(sAlo + ao + 16);
            uint32_t al3 = *(const uint32_t*)(sAlo + ao + 8 * STRIDE_A + 16);
#pragma unroll
            for (int in = 0; in < 12; ++in) {
                const uint32_t bo = boff + in * 8 * STRIDE_B + ks * 32;
                uint32_t bh0 = *(const uint32_t*)(sBhi + bo);
                uint32_t bh1 = *(const uint32_t*)(sBhi + bo + 16);
                uint32_t bl0 = *(const uint32_t*)(sBlo + bo);
                uint32_t bl1 = *(const uint32_t*)(sBlo + bo + 16);
                mma_bf16(acc[in], ah0, ah1, ah2, ah3, bh0, bh1);
                mma_bf16(acc[in], al0, al1, al2, al3, bh0, bh1);
                mma_bf16(acc[in], ah0, ah1, ah2, ah3, bl0, bl1);
            }
        }
        __syncthreads();
    }

    // ---- epilogue: + dstpart, GELU, column sums over this warp's 16 rows ----
    const int sn = wm >> 1;
#pragma unroll
    for (int in = 0; in < 12; ++in) {
        int c = wn * 96 + in * 8 + tg * 2;
        float2 d = *(const float2*)&sDst[sn * HIDDEN + c];
        float t0 = gelu_exact(acc[in][0] + d.x) + gelu_exact(acc[in][2] + d.x);
        float t1 = gelu_exact(acc[in][1] + d.y) + gelu_exact(acc[in][3] + d.y);
#pragma unroll
        for (int off = 4; off < 32; off <<= 1) {
            t0 += __shfl_xor_sync(0xffffffffu, t0, off);
            t1 += __shfl_xor_sync(0xffffffffu, t1, off);
        }
        if (lane < 4) {
            sCol[wm][c] = t0;
            sCol[wm][c + 1] = t1;
        }
    }
    __syncthreads();
    for (int i = tid; i < 2 * HIDDEN; i += 256) {
        int s = i / HIDDEN, n = i % HIDDEN;
        g_pooled[(b * 2 + s) * HIDDEN + n] =
            (sCol[s * 2][n] + sCol[s * 2 + 1][n]) * (1.0f / 32.0f);
    }
}

// ============================================================
// Kernel C: out = g_pooled @ W2 + b2  (32 rows / 128 threads)
// ============================================================
__global__ void __launch_bounds__(128)
out_gemm_kernel(const float* __restrict__ W2, const float* __restrict__ b2,
                float* __restrict__ out) {
    __shared__ float sX[32 * HIDDEN];
    const int tid = threadIdx.x;
    const int s0 = blockIdx.x * 32;

    for (int i = tid; i < 32 * HIDDEN; i += 128) sX[i] = g_pooled[s0 * HIDDEN + i];
    __syncthreads();

    const int r0 = (tid >> 5) * 8;
    const int n0 = (tid & 31) * 6;
    unsigned long long acc[8][3];
#pragma unroll
    for (int i = 0; i < 8; ++i)
#pragma unroll
        for (int j = 0; j < 3; ++j) acc[i][j] = 0ULL;
#pragma unroll 2
    for (int k = 0; k < HIDDEN; ++k) {
        const unsigned long long* bp = (const unsigned long long*)&W2[k * HIDDEN + n0];
        unsigned long long b0 = bp[0], bq = bp[1], b2_ = bp[2];
#pragma unroll
        for (int i = 0; i < 8; ++i) {
            unsigned long long a = dup2(sX[(r0 + i) * HIDDEN + k]);
            fma2(acc[i][0], a, b0);
            fma2(acc[i][1], a, bq);
            fma2(acc[i][2], a, b2_);
        }
    }
#pragma unroll
    for (int i = 0; i < 8; ++i) {
        float* o = &out[(s0 + r0 + i) * HIDDEN + n0];
#pragma unroll
        for (int j = 0; j < 3; ++j) {
            float2 v = unpack2(acc[i][j]);
            o[j * 2] = v.x + b2[n0 + j * 2];
            o[j * 2 + 1] = v.y + b2[n0 + j * 2 + 1];
        }
    }
}

// ============================================================
extern "C" void kernel_launch(void* const* d_in, const int* in_sizes, int n_in,
                              void* d_out, int out_size) {
    const float* feat = (const float*)d_in[0];
    const float* pos = (const float*)d_in[1];
    const int* src_idx = (const int*)d_in[2];
    const int* dst_idx = (const int*)d_in[3];
    const float* Win = (const float*)d_in[4];
    const float* bin = (const float*)d_in[5];
    const float* W1 = (const float*)d_in[6];
    const float* b1 = (const float*)d_in[7];
    const float* W2 = (const float*)d_in[8];
    const float* b2 = (const float*)d_in[9];
    float* out = (float*)d_out;

    const int E = in_sizes[2];
    const int S = E / MAXDEG;   // 8192

    w1_split_kernel<<<(HIDDEN * HIDDEN + 255) / 256, 256>>>(W1);
    dst_partial_kernel<<<S / 32, 128>>>(feat, pos, dst_idx, Win, bin, W1, b1);
    snp_mma_kernel<<<S / 2, 256>>>(feat, pos, src_idx, Win, bin);
    out_gemm_kernel<<<S / 32, 128>>>(W2, b2, out);
}

// round 6
// speedup vs baseline: 2.1930x; 1.1846x over previous
#include <cuda_runtime.h>
#include <cuda_bf16.h>
#include <cstdint>

#define HIDDEN 192
#define MAXDEG 32
#define MAX_S 8192

// scratch (device globals: allocation-free). 16B-aligned for vector ld/st.
__device__ __align__(16) float g_dstpart[MAX_S * HIDDEN];         // b1 + x_dst @ W1_bot
__device__ __align__(16) float g_pooled[MAX_S * HIDDEN];          // mean(gelu(...))
__device__ __align__(16) __nv_bfloat16 g_W1Thi[HIDDEN * HIDDEN];  // W1_top^T hi [n][k]
__device__ __align__(16) __nv_bfloat16 g_W1Tlo[HIDDEN * HIDDEN];  // W1_top^T lo
__device__ __align__(16) __nv_bfloat16 g_W1bThi[HIDDEN * HIDDEN]; // W1_bot^T hi
__device__ __align__(16) __nv_bfloat16 g_W1bTlo[HIDDEN * HIDDEN]; // W1_bot^T lo
__device__ __align__(16) __nv_bfloat16 g_W2Thi[HIDDEN * HIDDEN];  // W2^T hi
__device__ __align__(16) __nv_bfloat16 g_W2Tlo[HIDDEN * HIDDEN];  // W2^T lo

// ---------------- helpers ----------------
__device__ __forceinline__ float sin_poly(float x) {
    float x2 = x * x;
    float p = -1.98412698e-4f;
    p = fmaf(p, x2, 8.33333333e-3f);
    p = fmaf(p, x2, -1.66666667e-1f);
    return fmaf(x * x2, p, x);
}
__device__ __forceinline__ float cos_poly(float x) {
    float x2 = x * x;
    float p = 2.48015873e-5f;
    p = fmaf(p, x2, -1.38888889e-3f);
    p = fmaf(p, x2, 4.16666667e-2f);
    p = fmaf(p, x2, -0.5f);
    return fmaf(p, x2, 1.0f);
}
__device__ __forceinline__ float gelu_exact(float x) {
    return 0.5f * x * (1.0f + erff(x * 0.7071067811865476f));
}
__device__ __forceinline__ float embed_channel(int c, float f0, float f1, float f2,
                                               const float* pp, const float* sWin,
                                               const float* sBin, const float* sOmega) {
    float v = sBin[c];
    v = fmaf(f0, sWin[c], v);
    v = fmaf(f1, sWin[HIDDEN + c], v);
    v = fmaf(f2, sWin[2 * HIDDEN + c], v);
    int axis = c >> 6;
    int j = c & 63;
    float ang = pp[axis] * sOmega[j & 31];
    float e = (j < 32) ? sin_poly(ang) : cos_poly(ang);
    return v + e;
}
__device__ __forceinline__ void mma_bf16(float* c, uint32_t a0, uint32_t a1, uint32_t a2,
                                         uint32_t a3, uint32_t b0, uint32_t b1) {
    asm volatile(
        "mma.sync.aligned.m16n8k16.row.col.f32.bf16.bf16.f32 "
        "{%0,%1,%2,%3}, {%4,%5,%6,%7}, {%8,%9}, {%0,%1,%2,%3};"
        : "+f"(c[0]), "+f"(c[1]), "+f"(c[2]), "+f"(c[3])
        : "r"(a0), "r"(a1), "r"(a2), "r"(a3), "r"(b0), "r"(b1));
}
__device__ __forceinline__ uint32_t pack_bf16(float v0, float v1) {
    __nv_bfloat162 t;
    t.x = __float2bfloat16(v0);
    t.y = __float2bfloat16(v1);
    return *reinterpret_cast<uint32_t*>(&t);
}
__device__ __forceinline__ void split_bf16(float v, uint32_t& hi_out_half,
                                           float& lo_out) {
    __nv_bfloat16 h = __float2bfloat16(v);
    hi_out_half = (uint32_t)*reinterpret_cast<unsigned short*>(&h);
    lo_out = v - __bfloat162float(h);
}

#define STRIDE_A 72  // 32 bf16 (64B) + 8B pad
#define STRIDE_B 80  // 32 bf16 (64B) + 16B pad (rows 16B aligned)

// ============================================================
// Kernel P: split W1_top^T, W1_bot^T, W2^T into bf16 hi/lo
// ============================================================
__global__ void __launch_bounds__(256)
weight_split_kernel(const float* __restrict__ W1, const float* __restrict__ W2) {
    int i = blockIdx.x * 256 + threadIdx.x;
    if (i >= HIDDEN * HIDDEN) return;
    int k = i / HIDDEN, n = i % HIDDEN;
    {
        float w = W1[k * HIDDEN + n];
        __nv_bfloat16 hi = __float2bfloat16(w);
        g_W1Thi[n * HIDDEN + k] = hi;
        g_W1Tlo[n * HIDDEN + k] = __float2bfloat16(w - __bfloat162float(hi));
    }
    {
        float w = W1[(HIDDEN + k) * HIDDEN + n];
        __nv_bfloat16 hi = __float2bfloat16(w);
        g_W1bThi[n * HIDDEN + k] = hi;
        g_W1bTlo[n * HIDDEN + k] = __float2bfloat16(w - __bfloat162float(hi));
    }
    {
        float w = W2[k * HIDDEN + n];
        __nv_bfloat16 hi = __float2bfloat16(w);
        g_W2Thi[n * HIDDEN + k] = hi;
        g_W2Tlo[n * HIDDEN + k] = __float2bfloat16(w - __bfloat162float(hi));
    }
}

// ============================================================
// Kernel A: dst partial via MMA. CTA = 64 supernodes (M=64).
// g_dstpart[s][n] = b1[n] + embed(dst_s) @ W1_bot[:,n]
// ============================================================
__global__ void __launch_bounds__(256, 2)
dst_mma_kernel(const float* __restrict__ feat, const float* __restrict__ pos,
               const int* __restrict__ dst_idx, const float* __restrict__ Win,
               const float* __restrict__ bin, const float* __restrict__ b1) {
    __shared__ __align__(16) unsigned char sAhi[64 * STRIDE_A];
    __shared__ __align__(16) unsigned char sAlo[64 * STRIDE_A];
    __shared__ __align__(16) unsigned char sBhi[HIDDEN * STRIDE_B];
    __shared__ __align__(16) unsigned char sBlo[HIDDEN * STRIDE_B];
    __shared__ float sWin[3 * HIDDEN], sBin[HIDDEN], sOmega[32], sB1[HIDDEN];

    const int tid = threadIdx.x;
    const int lane = tid & 31;
    const int w = tid >> 5;
    const int wm = w & 3, wn = w >> 2;
    const int g = lane >> 2, tg = lane & 3;
    const int s0 = blockIdx.x * 64;

    for (int i = tid; i < 3 * HIDDEN; i += 256) sWin[i] = Win[i];
    for (int i = tid; i < HIDDEN; i += 256) sBin[i] = bin[i];
    for (int i = tid; i < HIDDEN; i += 256) sB1[i] = b1[i];
    if (tid < 32) sOmega[tid] = exp2f(-(float)tid * 0.4152410118609203f);

    float f0 = 0.f, f1 = 0.f, f2 = 0.f, pp[3] = {0.f, 0.f, 0.f};
    const int m = tid & 63;
    const int cg = (tid >> 6) & 1;
    if (tid < 128) {
        int node = dst_idx[(s0 + m) * MAXDEG];
        f0 = feat[node * 3]; f1 = feat[node * 3 + 1]; f2 = feat[node * 3 + 2];
        pp[0] = pos[node * 3]; pp[1] = pos[node * 3 + 1]; pp[2] = pos[node * 3 + 2];
    }
    __syncthreads();

    float acc[12][4];
#pragma unroll
    for (int i = 0; i < 12; ++i)
#pragma unroll
        for (int j = 0; j < 4; ++j) acc[i][j] = 0.0f;

    const uint32_t aoff = (uint32_t)(wm * 16 + g) * STRIDE_A + tg * 4;
    const uint32_t boff = (uint32_t)(wn * 96 + g) * STRIDE_B + tg * 4;

    for (int ch = 0; ch < 6; ++ch) {
        if (tid < 128) {
            const int jb = cg * 16;
#pragma unroll
            for (int j = 0; j < 16; j += 2) {
                int c0 = ch * 32 + jb + j;
                float v0 = embed_channel(c0, f0, f1, f2, pp, sWin, sBin, sOmega);
                float v1 = embed_channel(c0 + 1, f0, f1, f2, pp, sWin, sBin, sOmega);
                __nv_bfloat16 h0 = __float2bfloat16(v0);
                __nv_bfloat16 h1 = __float2bfloat16(v1);
                float l0 = v0 - __bfloat162float(h0);
                float l1 = v1 - __bfloat162float(h1);
                __nv_bfloat162 hp; hp.x = h0; hp.y = h1;
                *(uint32_t*)(sAhi + m * STRIDE_A + (jb + j) * 2) =
                    *reinterpret_cast<uint32_t*>(&hp);
                *(uint32_t*)(sAlo + m * STRIDE_A + (jb + j) * 2) = pack_bf16(l0, l1);
            }
        } else {
            const int t2 = tid - 128;
#pragma unroll
            for (int i = 0; i < 12; ++i) {
                int isLo = i >= 6;
                int id = t2 + 128 * (isLo ? (i - 6) : i);
                int n = id >> 2, seg = id & 3;
                const __nv_bfloat16* src =
                    (isLo ? g_W1bTlo : g_W1bThi) + n * HIDDEN + ch * 32 + seg * 8;
                unsigned char* dst = (isLo ? sBlo : sBhi) + n * STRIDE_B + seg * 16;
                *reinterpret_cast<uint4*>(dst) = *reinterpret_cast<const uint4*>(src);
            }
        }
        __syncthreads();

#pragma unroll
        for (int ks = 0; ks < 2; ++ks) {
            const uint32_t ao = aoff + ks * 32;
            uint32_t ah0 = *(const uint32_t*)(sAhi + ao);
            uint32_t ah1 = *(const uint32_t*)(sAhi + ao + 8 * STRIDE_A);
            uint32_t ah2 = *(const uint32_t*)(sAhi + ao + 16);
            uint32_t ah3 = *(const uint32_t*)(sAhi + ao + 8 * STRIDE_A + 16);
            uint32_t al0 = *(const uint32_t*)(sAlo + ao);
            uint32_t al1 = *(const uint32_t*)(sAlo + ao + 8 * STRIDE_A);
            uint32_t al2 = *(const uint32_t*)(sAlo + ao + 16);
            uint32_t al3 = *(const uint32_t*)(sAlo + ao + 8 * STRIDE_A + 16);
#pragma unroll
            for (int in = 0; in < 12; ++in) {
                const uint32_t bo = boff + in * 8 * STRIDE_B + ks * 32;
                uint32_t bh0 = *(const uint32_t*)(sBhi + bo);
                uint32_t bh1 = *(const uint32_t*)(sBhi + bo + 16);
                uint32_t bl0 = *(const uint32_t*)(sBlo + bo);
                uint32_t bl1 = *(const uint32_t*)(sBlo + bo + 16);
                mma_bf16(acc[in], ah0, ah1, ah2, ah3, bh0, bh1);
                mma_bf16(acc[in], al0, al1, al2, al3, bh0, bh1);
                mma_bf16(acc[in], ah0, ah1, ah2, ah3, bl0, bl1);
            }
        }
        __syncthreads();
    }

    // epilogue: + b1, direct stores
    const int r_hi = s0 + wm * 16 + g;
#pragma unroll
    for (int in = 0; in < 12; ++in) {
        int c = wn * 96 + in * 8 + tg * 2;
        float2 bb = *(const float2*)&sB1[c];
        float2 v0 = {acc[in][0] + bb.x, acc[in][1] + bb.y};
        float2 v1 = {acc[in][2] + bb.x, acc[in][3] + bb.y};
        *(float2*)&g_dstpart[r_hi * HIDDEN + c] = v0;
        *(float2*)&g_dstpart[(r_hi + 8) * HIDDEN + c] = v1;
    }
}

// ============================================================
// Kernel B: mma.sync bf16 3-term edge GEMM + GELU + pooled mean
// CTA = 2 supernodes (M=64), 256 threads (unchanged from R5)
// ============================================================
__global__ void __launch_bounds__(256, 2)
snp_mma_kernel(const float* __restrict__ feat, const float* __restrict__ pos,
               const int* __restrict__ src_idx, const float* __restrict__ Win,
               const float* __restrict__ bin) {
    __shared__ __align__(16) unsigned char sAhi[64 * STRIDE_A];
    __shared__ __align__(16) unsigned char sAlo[64 * STRIDE_A];
    __shared__ __align__(16) unsigned char sBhi[HIDDEN * STRIDE_B];
    __shared__ __align__(16) unsigned char sBlo[HIDDEN * STRIDE_B];
    __shared__ float sWin[3 * HIDDEN], sBin[HIDDEN], sOmega[32];
    __shared__ float sDst[2 * HIDDEN];
    __shared__ float sCol[4][HIDDEN];

    const int b = blockIdx.x;
    const int tid = threadIdx.x;
    const int lane = tid & 31;
    const int w = tid >> 5;
    const int wm = w & 3, wn = w >> 2;
    const int g = lane >> 2, tg = lane & 3;

    for (int i = tid; i < 3 * HIDDEN; i += 256) sWin[i] = Win[i];
    for (int i = tid; i < HIDDEN; i += 256) sBin[i] = bin[i];
    for (int i = tid; i < 2 * HIDDEN; i += 256) sDst[i] = g_dstpart[b * 2 * HIDDEN + i];
    if (tid < 32) sOmega[tid] = exp2f(-(float)tid * 0.4152410118609203f);

    float f0 = 0.f, f1 = 0.f, f2 = 0.f, pp[3] = {0.f, 0.f, 0.f};
    const int m = tid & 63;
    const int cg = (tid >> 6) & 1;
    if (tid < 128) {
        int node = src_idx[b * 64 + m];
        f0 = feat[node * 3]; f1 = feat[node * 3 + 1]; f2 = feat[node * 3 + 2];
        pp[0] = pos[node * 3]; pp[1] = pos[node * 3 + 1]; pp[2] = pos[node * 3 + 2];
    }
    __syncthreads();

    float acc[12][4];
#pragma unroll
    for (int i = 0; i < 12; ++i)
#pragma unroll
        for (int j = 0; j < 4; ++j) acc[i][j] = 0.0f;

    const uint32_t aoff = (uint32_t)(wm * 16 + g) * STRIDE_A + tg * 4;
    const uint32_t boff = (uint32_t)(wn * 96 + g) * STRIDE_B + tg * 4;

    for (int ch = 0; ch < 6; ++ch) {
        if (tid < 128) {
            const int jb = cg * 16;
#pragma unroll
            for (int j = 0; j < 16; j += 2) {
                int c0 = ch * 32 + jb + j;
                float v0 = embed_channel(c0, f0, f1, f2, pp, sWin, sBin, sOmega);
                float v1 = embed_channel(c0 + 1, f0, f1, f2, pp, sWin, sBin, sOmega);
                __nv_bfloat16 h0 = __float2bfloat16(v0);
                __nv_bfloat16 h1 = __float2bfloat16(v1);
                float l0 = v0 - __bfloat162float(h0);
                float l1 = v1 - __bfloat162float(h1);
                __nv_bfloat162 hp; hp.x = h0; hp.y = h1;
                *(uint32_t*)(sAhi + m * STRIDE_A + (jb + j) * 2) =
                    *reinterpret_cast<uint32_t*>(&hp);
                *(uint32_t*)(sAlo + m * STRIDE_A + (jb + j) * 2) = pack_bf16(l0, l1);
            }
        } else {
            const int t2 = tid - 128;
#pragma unroll
            for (int i = 0; i < 12; ++i) {
                int isLo = i >= 6;
                int id = t2 + 128 * (isLo ? (i - 6) : i);
                int n = id >> 2, seg = id & 3;
                const __nv_bfloat16* src =
                    (isLo ? g_W1Tlo : g_W1Thi) + n * HIDDEN + ch * 32 + seg * 8;
                unsigned char* dst = (isLo ? sBlo : sBhi) + n * STRIDE_B + seg * 16;
                *reinterpret_cast<uint4*>(dst) = *reinterpret_cast<const uint4*>(src);
            }
        }
        __syncthreads();

#pragma unroll
        for (int ks = 0; ks < 2; ++ks) {
            const uint32_t ao = aoff + ks * 32;
            uint32_t ah0 = *(const uint32_t*)(sAhi + ao);
            uint32_t ah1 = *(const uint32_t*)(sAhi + ao + 8 * STRIDE_A);
            uint32_t ah2 = *(const uint32_t*)(sAhi + ao + 16);
            uint32_t ah3 = *(const uint32_t*)(sAhi + ao + 8 * STRIDE_A + 16);
            uint32_t al0 = *(const uint32_t*)(sAlo + ao);
            uint32_t al1 = *(const uint32_t*)(sAlo + ao + 8 * STRIDE_A);
            uint32_t al2 = *(const uint32_t*)(sAlo + ao + 16);
            uint32_t al3 = *(const uint32_t*)(sAlo + ao + 8 * STRIDE_A + 16);
#pragma unroll
            for (int in = 0; in < 12; ++in) {
                const uint32_t bo = boff + in * 8 * STRIDE_B + ks * 32;
                uint32_t bh0 = *(const uint32_t*)(sBhi + bo);
                uint32_t bh1 = *(const uint32_t*)(sBhi + bo + 16);
                uint32_t bl0 = *(const uint32_t*)(sBlo + bo);
                uint32_t bl1 = *(const uint32_t*)(sBlo + bo + 16);
                mma_bf16(acc[in], ah0, ah1, ah2, ah3, bh0, bh1);
                mma_bf16(acc[in], al0, al1, al2, al3, bh0, bh1);
                mma_bf16(acc[in], ah0, ah1, ah2, ah3, bl0, bl1);
            }
        }
        __syncthreads();
    }

    const int sn = wm >> 1;
#pragma unroll
    for (int in = 0; in < 12; ++in) {
        int c = wn * 96 + in * 8 + tg * 2;
        float2 d = *(const float2*)&sDst[sn * HIDDEN + c];
        float t0 = gelu_exact(acc[in][0] + d.x) + gelu_exact(acc[in][2] + d.x);
        float t1 = gelu_exact(acc[in][1] + d.y) + gelu_exact(acc[in][3] + d.y);
#pragma unroll
        for (int off = 4; off < 32; off <<= 1) {
            t0 += __shfl_xor_sync(0xffffffffu, t0, off);
            t1 += __shfl_xor_sync(0xffffffffu, t1, off);
        }
        if (lane < 4) {
            sCol[wm][c] = t0;
            sCol[wm][c + 1] = t1;
        }
    }
    __syncthreads();
    for (int i = tid; i < 2 * HIDDEN; i += 256) {
        int s = i / HIDDEN, n = i % HIDDEN;
        g_pooled[(b * 2 + s) * HIDDEN + n] =
            (sCol[s * 2][n] + sCol[s * 2 + 1][n]) * (1.0f / 32.0f);
    }
}

// ============================================================
// Kernel C: out = g_pooled @ W2 + b2 via MMA. CTA = 64 rows.
// ============================================================
__global__ void __launch_bounds__(256, 2)
out_mma_kernel(const float* __restrict__ b2, float* __restrict__ out) {
    __shared__ __align__(16) unsigned char sAhi[64 * STRIDE_A];
    __shared__ __align__(16) unsigned char sAlo[64 * STRIDE_A];
    __shared__ __align__(16) unsigned char sBhi[HIDDEN * STRIDE_B];
    __shared__ __align__(16) unsigned char sBlo[HIDDEN * STRIDE_B];
    __shared__ float sB2[HIDDEN];

    const int tid = threadIdx.x;
    const int lane = tid & 31;
    const int w = tid >> 5;
    const int wm = w & 3, wn = w >> 2;
    const int g = lane >> 2, tg = lane & 3;
    const int s0 = blockIdx.x * 64;

    for (int i = tid; i < HIDDEN; i += 256) sB2[i] = b2[i];

    const int m = tid & 63;
    const int cg = (tid >> 6) & 1;

    float acc[12][4];
#pragma unroll
    for (int i = 0; i < 12; ++i)
#pragma unroll
        for (int j = 0; j < 4; ++j) acc[i][j] = 0.0f;

    const uint32_t aoff = (uint32_t)(wm * 16 + g) * STRIDE_A + tg * 4;
    const uint32_t boff = (uint32_t)(wn * 96 + g) * STRIDE_B + tg * 4;

    for (int ch = 0; ch < 6; ++ch) {
        if (tid < 128) {
            const int jb = cg * 16;
            const float* arow = g_pooled + (s0 + m) * HIDDEN + ch * 32 + jb;
#pragma unroll
            for (int j = 0; j < 16; j += 2) {
                float2 v = *(const float2*)&arow[j];
                __nv_bfloat16 h0 = __float2bfloat16(v.x);
                __nv_bfloat16 h1 = __float2bfloat16(v.y);
                float l0 = v.x - __bfloat162float(h0);
                float l1 = v.y - __bfloat162float(h1);
                __nv_bfloat162 hp; hp.x = h0; hp.y = h1;
                *(uint32_t*)(sAhi + m * STRIDE_A + (jb + j) * 2) =
                    *reinterpret_cast<uint32_t*>(&hp);
                *(uint32_t*)(sAlo + m * STRIDE_A + (jb + j) * 2) = pack_bf16(l0, l1);
            }
        } else {
            const int t2 = tid - 128;
#pragma unroll
            for (int i = 0; i < 12; ++i) {
                int isLo = i >= 6;
                int id = t2 + 128 * (isLo ? (i - 6) : i);
                int n = id >> 2, seg = id & 3;
                const __nv_bfloat16* src =
                    (isLo ? g_W2Tlo : g_W2Thi) + n * HIDDEN + ch * 32 + seg * 8;
                unsigned char* dst = (isLo ? sBlo : sBhi) + n * STRIDE_B + seg * 16;
                *reinterpret_cast<uint4*>(dst) = *reinterpret_cast<const uint4*>(src);
            }
        }
        __syncthreads();

#pragma unroll
        for (int ks = 0; ks < 2; ++ks) {
            const uint32_t ao = aoff + ks * 32;
            uint32_t ah0 = *(const uint32_t*)(sAhi + ao);
            uint32_t ah1 = *(const uint32_t*)(sAhi + ao + 8 * STRIDE_A);
            uint32_t ah2 = *(const uint32_t*)(sAhi + ao + 16);
            uint32_t ah3 = *(const uint32_t*)(sAhi + ao + 8 * STRIDE_A + 16);
            uint32_t al0 = *(const uint32_t*)(sAlo + ao);
            uint32_t al1 = *(const uint32_t*)(sAlo + ao + 8 * STRIDE_A);
            uint32_t al2 = *(const uint32_t*)(sAlo + ao + 16);
            uint32_t al3 = *(const uint32_t*)(sAlo + ao + 8 * STRIDE_A + 16);
#pragma unroll
            for (int in = 0; in < 12; ++in) {
                const uint32_t bo = boff + in * 8 * STRIDE_B + ks * 32;
                uint32_t bh0 = *(const uint32_t*)(sBhi + bo);
                uint32_t bh1 = *(const uint32_t*)(sBhi + bo + 16);
                uint32_t bl0 = *(const uint32_t*)(sBlo + bo);
                uint32_t bl1 = *(const uint32_t*)(sBlo + bo + 16);
                mma_bf16(acc[in], ah0, ah1, ah2, ah3, bh0, bh1);
                mma_bf16(acc[in], al0, al1, al2, al3, bh0, bh1);
                mma_bf16(acc[in], ah0, ah1, ah2, ah3, bl0, bl1);
            }
        }
        __syncthreads();
    }

    const int r_hi = s0 + wm * 16 + g;
#pragma unroll
    for (int in = 0; in < 12; ++in) {
        int c = wn * 96 + in * 8 + tg * 2;
        float2 bb = *(const float2*)&sB2[c];
        float2 v0 = {acc[in][0] + bb.x, acc[in][1] + bb.y};
        float2 v1 = {acc[in][2] + bb.x, acc[in][3] + bb.y};
        *(float2*)&out[r_hi * HIDDEN + c] = v0;
        *(float2*)&out[(r_hi + 8) * HIDDEN + c] = v1;
    }
}

// ============================================================
extern "C" void kernel_launch(void* const* d_in, const int* in_sizes, int n_in,
                              void* d_out, int out_size) {
    const float* feat = (const float*)d_in[0];
    const float* pos = (const float*)d_in[1];
    const int* src_idx = (const int*)d_in[2];
    const int* dst_idx = (const int*)d_in[3];
    const float* Win = (const float*)d_in[4];
    const float* bin = (const float*)d_in[5];
    const float* W1 = (const float*)d_in[6];
    const float* b1 = (const float*)d_in[7];
    const float* W2 = (const float*)d_in[8];
    const float* b2 = (const float*)d_in[9];
    float* out = (float*)d_out;

    const int E = in_sizes[2];
    const int S = E / MAXDEG;   // 8192

    weight_split_kernel<<<(HIDDEN * HIDDEN + 255) / 256, 256>>>(W1, W2);
    dst_mma_kernel<<<S / 64, 256>>>(feat, pos, dst_idx, Win, bin, b1);
    snp_mma_kernel<<<S / 2, 256>>>(feat, pos, src_idx, Win, bin);
    out_mma_kernel<<<S / 64, 256>>>(b2, out);
}

// round 7
// speedup vs baseline: 2.3311x; 1.0630x over previous
#include <cuda_runtime.h>
#include <cuda_bf16.h>
#include <cstdint>

#define HIDDEN 192
#define MAXDEG 32
#define MAX_S 8192

// scratch (device globals: allocation-free). 16B-aligned for vector ld/st + cp.async.
__device__ __align__(16) float g_dstpart[MAX_S * HIDDEN];         // b1 + x_dst @ W1_bot
__device__ __align__(16) float g_pooled[MAX_S * HIDDEN];          // mean(gelu(...))
__device__ __align__(16) __nv_bfloat16 g_W1Thi[HIDDEN * HIDDEN];  // W1_top^T hi [n][k]
__device__ __align__(16) __nv_bfloat16 g_W1Tlo[HIDDEN * HIDDEN];  // W1_top^T lo
__device__ __align__(16) __nv_bfloat16 g_W1bThi[HIDDEN * HIDDEN]; // W1_bot^T hi
__device__ __align__(16) __nv_bfloat16 g_W1bTlo[HIDDEN * HIDDEN]; // W1_bot^T lo
__device__ __align__(16) __nv_bfloat16 g_W2Thi[HIDDEN * HIDDEN];  // W2^T hi
__device__ __align__(16) __nv_bfloat16 g_W2Tlo[HIDDEN * HIDDEN];  // W2^T lo

// ---------------- helpers ----------------
__device__ __forceinline__ float sin_poly(float x) {
    float x2 = x * x;
    float p = -1.98412698e-4f;
    p = fmaf(p, x2, 8.33333333e-3f);
    p = fmaf(p, x2, -1.66666667e-1f);
    return fmaf(x * x2, p, x);
}
__device__ __forceinline__ float cos_poly(float x) {
    float x2 = x * x;
    float p = 2.48015873e-5f;
    p = fmaf(p, x2, -1.38888889e-3f);
    p = fmaf(p, x2, 4.16666667e-2f);
    p = fmaf(p, x2, -0.5f);
    return fmaf(p, x2, 1.0f);
}
__device__ __forceinline__ float gelu_exact(float x) {
    return 0.5f * x * (1.0f + erff(x * 0.7071067811865476f));
}
__device__ __forceinline__ float embed_channel(int c, float f0, float f1, float f2,
                                               const float* pp, const float* sWin,
                                               const float* sBin, const float* sOmega) {
    float v = sBin[c];
    v = fmaf(f0, sWin[c], v);
    v = fmaf(f1, sWin[HIDDEN + c], v);
    v = fmaf(f2, sWin[2 * HIDDEN + c], v);
    int axis = c >> 6;
    int j = c & 63;
    float ang = pp[axis] * sOmega[j & 31];
    float e = (j < 32) ? sin_poly(ang) : cos_poly(ang);
    return v + e;
}
__device__ __forceinline__ void mma_bf16(float* c, uint32_t a0, uint32_t a1, uint32_t a2,
                                         uint32_t a3, uint32_t b0, uint32_t b1) {
    asm volatile(
        "mma.sync.aligned.m16n8k16.row.col.f32.bf16.bf16.f32 "
        "{%0,%1,%2,%3}, {%4,%5,%6,%7}, {%8,%9}, {%0,%1,%2,%3};"
        : "+f"(c[0]), "+f"(c[1]), "+f"(c[2]), "+f"(c[3])
        : "r"(a0), "r"(a1), "r"(a2), "r"(a3), "r"(b0), "r"(b1));
}
__device__ __forceinline__ uint32_t pack_bf16(float v0, float v1) {
    __nv_bfloat162 t;
    t.x = __float2bfloat16(v0);
    t.y = __float2bfloat16(v1);
    return *reinterpret_cast<uint32_t*>(&t);
}
__device__ __forceinline__ uint32_t smem_u32(const void* p) {
    uint32_t a;
    asm("{ .reg .u64 t; cvta.to.shared.u64 t, %1; cvt.u32.u64 %0, t; }" : "=r"(a) : "l"(p));
    return a;
}
__device__ __forceinline__ void cp_async16(void* dst_smem, const void* src) {
    uint32_t d = smem_u32(dst_smem);
    asm volatile("cp.async.cg.shared.global [%0], [%1], 16;" :: "r"(d), "l"(src) : "memory");
}
__device__ __forceinline__ void cp_async_commit() {
    asm volatile("cp.async.commit_group;" ::: "memory");
}
__device__ __forceinline__ void cp_async_wait0() {
    asm volatile("cp.async.wait_group 0;" ::: "memory");
}

#define STRIDE_A 72  // 32 bf16 (64B) + 8B pad
#define STRIDE_B 80  // 32 bf16 (64B) + 16B pad (rows 16B aligned)

// ============================================================
// Kernel P: split W1_top^T, W1_bot^T, W2^T into bf16 hi/lo
// ============================================================
__global__ void __launch_bounds__(256)
weight_split_kernel(const float* __restrict__ W1, const float* __restrict__ W2) {
    int i = blockIdx.x * 256 + threadIdx.x;
    if (i >= HIDDEN * HIDDEN) return;
    int k = i / HIDDEN, n = i % HIDDEN;
    {
        float w = W1[k * HIDDEN + n];
        __nv_bfloat16 hi = __float2bfloat16(w);
        g_W1Thi[n * HIDDEN + k] = hi;
        g_W1Tlo[n * HIDDEN + k] = __float2bfloat16(w - __bfloat162float(hi));
    }
    {
        float w = W1[(HIDDEN + k) * HIDDEN + n];
        __nv_bfloat16 hi = __float2bfloat16(w);
        g_W1bThi[n * HIDDEN + k] = hi;
        g_W1bTlo[n * HIDDEN + k] = __float2bfloat16(w - __bfloat162float(hi));
    }
    {
        float w = W2[k * HIDDEN + n];
        __nv_bfloat16 hi = __float2bfloat16(w);
        g_W2Thi[n * HIDDEN + k] = hi;
        g_W2Tlo[n * HIDDEN + k] = __float2bfloat16(w - __bfloat162float(hi));
    }
}

// ============================================================
// Kernel A: dst partial via MMA. CTA = 64 supernodes (M=64).
// (unchanged from R6 — proven)
// ============================================================
__global__ void __launch_bounds__(256, 2)
dst_mma_kernel(const float* __restrict__ feat, const float* __restrict__ pos,
               const int* __restrict__ dst_idx, const float* __restrict__ Win,
               const float* __restrict__ bin, const float* __restrict__ b1) {
    __shared__ __align__(16) unsigned char sAhi[64 * STRIDE_A];
    __shared__ __align__(16) unsigned char sAlo[64 * STRIDE_A];
    __shared__ __align__(16) unsigned char sBhi[HIDDEN * STRIDE_B];
    __shared__ __align__(16) unsigned char sBlo[HIDDEN * STRIDE_B];
    __shared__ float sWin[3 * HIDDEN], sBin[HIDDEN], sOmega[32], sB1[HIDDEN];

    const int tid = threadIdx.x;
    const int lane = tid & 31;
    const int w = tid >> 5;
    const int wm = w & 3, wn = w >> 2;
    const int g = lane >> 2, tg = lane & 3;
    const int s0 = blockIdx.x * 64;

    for (int i = tid; i < 3 * HIDDEN; i += 256) sWin[i] = Win[i];
    for (int i = tid; i < HIDDEN; i += 256) sBin[i] = bin[i];
    for (int i = tid; i < HIDDEN; i += 256) sB1[i] = b1[i];
    if (tid < 32) sOmega[tid] = exp2f(-(float)tid * 0.4152410118609203f);

    float f0 = 0.f, f1 = 0.f, f2 = 0.f, pp[3] = {0.f, 0.f, 0.f};
    const int m = tid & 63;
    const int cg = (tid >> 6) & 1;
    if (tid < 128) {
        int node = dst_idx[(s0 + m) * MAXDEG];
        f0 = feat[node * 3]; f1 = feat[node * 3 + 1]; f2 = feat[node * 3 + 2];
        pp[0] = pos[node * 3]; pp[1] = pos[node * 3 + 1]; pp[2] = pos[node * 3 + 2];
    }
    __syncthreads();

    float acc[12][4];
#pragma unroll
    for (int i = 0; i < 12; ++i)
#pragma unroll
        for (int j = 0; j < 4; ++j) acc[i][j] = 0.0f;

    const uint32_t aoff = (uint32_t)(wm * 16 + g) * STRIDE_A + tg * 4;
    const uint32_t boff = (uint32_t)(wn * 96 + g) * STRIDE_B + tg * 4;

    for (int ch = 0; ch < 6; ++ch) {
        if (tid < 128) {
            const int jb = cg * 16;
#pragma unroll
            for (int j = 0; j < 16; j += 2) {
                int c0 = ch * 32 + jb + j;
                float v0 = embed_channel(c0, f0, f1, f2, pp, sWin, sBin, sOmega);
                float v1 = embed_channel(c0 + 1, f0, f1, f2, pp, sWin, sBin, sOmega);
                __nv_bfloat16 h0 = __float2bfloat16(v0);
                __nv_bfloat16 h1 = __float2bfloat16(v1);
                float l0 = v0 - __bfloat162float(h0);
                float l1 = v1 - __bfloat162float(h1);
                __nv_bfloat162 hp; hp.x = h0; hp.y = h1;
                *(uint32_t*)(sAhi + m * STRIDE_A + (jb + j) * 2) =
                    *reinterpret_cast<uint32_t*>(&hp);
                *(uint32_t*)(sAlo + m * STRIDE_A + (jb + j) * 2) = pack_bf16(l0, l1);
            }
        } else {
            const int t2 = tid - 128;
#pragma unroll
            for (int i = 0; i < 12; ++i) {
                int isLo = i >= 6;
                int id = t2 + 128 * (isLo ? (i - 6) : i);
                int n = id >> 2, seg = id & 3;
                const __nv_bfloat16* src =
                    (isLo ? g_W1bTlo : g_W1bThi) + n * HIDDEN + ch * 32 + seg * 8;
                unsigned char* dst = (isLo ? sBlo : sBhi) + n * STRIDE_B + seg * 16;
                *reinterpret_cast<uint4*>(dst) = *reinterpret_cast<const uint4*>(src);
            }
        }
        __syncthreads();

#pragma unroll
        for (int ks = 0; ks < 2; ++ks) {
            const uint32_t ao = aoff + ks * 32;
            uint32_t ah0 = *(const uint32_t*)(sAhi + ao);
            uint32_t ah1 = *(const uint32_t*)(sAhi + ao + 8 * STRIDE_A);
            uint32_t ah2 = *(const uint32_t*)(sAhi + ao + 16);
            uint32_t ah3 = *(const uint32_t*)(sAhi + ao + 8 * STRIDE_A + 16);
            uint32_t al0 = *(const uint32_t*)(sAlo + ao);
            uint32_t al1 = *(const uint32_t*)(sAlo + ao + 8 * STRIDE_A);
            uint32_t al2 = *(const uint32_t*)(sAlo + ao + 16);
            uint32_t al3 = *(const uint32_t*)(sAlo + ao + 8 * STRIDE_A + 16);
#pragma unroll
            for (int in = 0; in < 12; ++in) {
                const uint32_t bo = boff + in * 8 * STRIDE_B + ks * 32;
                uint32_t bh0 = *(const uint32_t*)(sBhi + bo);
                uint32_t bh1 = *(const uint32_t*)(sBhi + bo + 16);
                uint32_t bl0 = *(const uint32_t*)(sBlo + bo);
                uint32_t bl1 = *(const uint32_t*)(sBlo + bo + 16);
                mma_bf16(acc[in], ah0, ah1, ah2, ah3, bh0, bh1);
                mma_bf16(acc[in], al0, al1, al2, al3, bh0, bh1);
                mma_bf16(acc[in], ah0, ah1, ah2, ah3, bl0, bl1);
            }
        }
        __syncthreads();
    }

    const int r_hi = s0 + wm * 16 + g;
#pragma unroll
    for (int in = 0; in < 12; ++in) {
        int c = wn * 96 + in * 8 + tg * 2;
        float2 bb = *(const float2*)&sB1[c];
        float2 v0 = {acc[in][0] + bb.x, acc[in][1] + bb.y};
        float2 v1 = {acc[in][2] + bb.x, acc[in][3] + bb.y};
        *(float2*)&g_dstpart[r_hi * HIDDEN + c] = v0;
        *(float2*)&g_dstpart[(r_hi + 8) * HIDDEN + c] = v1;
    }
}

// ============================================================
// Kernel B (R7): pipelined snp_mma — double buffer, 1 sync/chunk,
// cp.async B moves hidden under MMAs. Dynamic smem (~87KB).
// ============================================================
#define AB (64 * STRIDE_A)        // 4608
#define BBUF (HIDDEN * STRIDE_B)  // 15360
#define OFF_AHI 0
#define OFF_ALO (2 * AB)                 // 9216
#define OFF_BHI (4 * AB)                 // 18432
#define OFF_BLO (4 * AB + 2 * BBUF)      // 49152
#define OFF_WIN (4 * AB + 4 * BBUF)      // 79872
#define OFF_BIN (OFF_WIN + 3 * HIDDEN * 4)
#define OFF_OMG (OFF_BIN + HIDDEN * 4)
#define OFF_DST (OFF_OMG + 128)
#define OFF_COL (OFF_DST + 2 * HIDDEN * 4)
#define SMEMB_TOTAL (OFF_COL + 4 * HIDDEN * 4)   // 86912

__device__ __forceinline__ void produce_A(unsigned char* aHi, unsigned char* aLo, int ch,
                                          int m, int jb, float f0, float f1, float f2,
                                          const float* pp, const float* sWin,
                                          const float* sBin, const float* sOmega) {
#pragma unroll
    for (int j = 0; j < 16; j += 2) {
        int c0 = ch * 32 + jb + j;
        float v0 = embed_channel(c0, f0, f1, f2, pp, sWin, sBin, sOmega);
        float v1 = embed_channel(c0 + 1, f0, f1, f2, pp, sWin, sBin, sOmega);
        __nv_bfloat16 h0 = __float2bfloat16(v0);
        __nv_bfloat16 h1 = __float2bfloat16(v1);
        float l0 = v0 - __bfloat162float(h0);
        float l1 = v1 - __bfloat162float(h1);
        __nv_bfloat162 hp; hp.x = h0; hp.y = h1;
        *(uint32_t*)(aHi + m * STRIDE_A + (jb + j) * 2) = *reinterpret_cast<uint32_t*>(&hp);
        *(uint32_t*)(aLo + m * STRIDE_A + (jb + j) * 2) = pack_bf16(l0, l1);
    }
}

__device__ __forceinline__ void copy_B_async(unsigned char* bHi, unsigned char* bLo,
                                             int ch, int t2) {
#pragma unroll
    for (int i = 0; i < 12; ++i) {
        int isLo = i >= 6;
        int id = t2 + 128 * (isLo ? (i - 6) : i);   // 0..767
        int n = id >> 2, seg = id & 3;
        const __nv_bfloat16* src =
            (isLo ? g_W1Tlo : g_W1Thi) + n * HIDDEN + ch * 32 + seg * 8;
        unsigned char* dst = (isLo ? bLo : bHi) + n * STRIDE_B + seg * 16;
        cp_async16(dst, src);
    }
}

__global__ void __launch_bounds__(256, 2)
snp_mma_kernel(const float* __restrict__ feat, const float* __restrict__ pos,
               const int* __restrict__ src_idx, const float* __restrict__ Win,
               const float* __restrict__ bin) {
    extern __shared__ __align__(16) unsigned char sm[];
    float* sWin = (float*)(sm + OFF_WIN);
    float* sBin = (float*)(sm + OFF_BIN);
    float* sOmega = (float*)(sm + OFF_OMG);
    float* sDst = (float*)(sm + OFF_DST);
    float* sCol = (float*)(sm + OFF_COL);   // [4][HIDDEN]

    const int b = blockIdx.x;
    const int tid = threadIdx.x;
    const int lane = tid & 31;
    const int w = tid >> 5;
    const int wm = w & 3, wn = w >> 2;
    const int g = lane >> 2, tg = lane & 3;

    for (int i = tid; i < 3 * HIDDEN; i += 256) sWin[i] = Win[i];
    for (int i = tid; i < HIDDEN; i += 256) sBin[i] = bin[i];
    for (int i = tid; i < 2 * HIDDEN; i += 256) sDst[i] = g_dstpart[b * 2 * HIDDEN + i];
    if (tid < 32) sOmega[tid] = exp2f(-(float)tid * 0.4152410118609203f);

    float f0 = 0.f, f1 = 0.f, f2 = 0.f, pp[3] = {0.f, 0.f, 0.f};
    const int m = tid & 63;
    const int jb = ((tid >> 6) & 1) * 16;
    if (tid < 128) {
        int node = src_idx[b * 64 + m];
        f0 = feat[node * 3]; f1 = feat[node * 3 + 1]; f2 = feat[node * 3 + 2];
        pp[0] = pos[node * 3]; pp[1] = pos[node * 3 + 1]; pp[2] = pos[node * 3 + 2];
    }
    const int t2 = tid - 128;
    __syncthreads();   // consts ready (producers read sWin/sBin/sOmega)

    float acc[12][4];
#pragma unroll
    for (int i = 0; i < 12; ++i)
#pragma unroll
        for (int j = 0; j < 4; ++j) acc[i][j] = 0.0f;

    const uint32_t aoff = (uint32_t)(wm * 16 + g) * STRIDE_A + tg * 4;
    const uint32_t boff = (uint32_t)(wn * 96 + g) * STRIDE_B + tg * 4;

    // ---- prologue: fill buffer 0 with chunk 0 ----
    if (tid < 128) {
        produce_A(sm + OFF_AHI, sm + OFF_ALO, 0, m, jb, f0, f1, f2, pp, sWin, sBin, sOmega);
    } else {
        copy_B_async(sm + OFF_BHI, sm + OFF_BLO, 0, t2);
        cp_async_commit();
        cp_async_wait0();
    }
    __syncthreads();

    // ---- pipelined main loop: produce(c+1) overlaps MMA(c) ----
    for (int c = 0; c < 6; ++c) {
        const int cur = c & 1;
        const int nxt = (c + 1) & 1;
        if (c < 5) {
            if (tid < 128) {
                produce_A(sm + OFF_AHI + nxt * AB, sm + OFF_ALO + nxt * AB, c + 1, m, jb,
                          f0, f1, f2, pp, sWin, sBin, sOmega);
            } else {
                copy_B_async(sm + OFF_BHI + nxt * BBUF, sm + OFF_BLO + nxt * BBUF, c + 1, t2);
                cp_async_commit();
            }
        }

        const unsigned char* aHi = sm + OFF_AHI + cur * AB;
        const unsigned char* aLo = sm + OFF_ALO + cur * AB;
        const unsigned char* bHi = sm + OFF_BHI + cur * BBUF;
        const unsigned char* bLo = sm + OFF_BLO + cur * BBUF;
#pragma unroll
        for (int ks = 0; ks < 2; ++ks) {
            const uint32_t ao = aoff + ks * 32;
            uint32_t ah0 = *(const uint32_t*)(aHi + ao);
            uint32_t ah1 = *(const uint32_t*)(aHi + ao + 8 * STRIDE_A);
            uint32_t ah2 = *(const uint32_t*)(aHi + ao + 16);
            uint32_t ah3 = *(const uint32_t*)(aHi + ao + 8 * STRIDE_A + 16);
            uint32_t al0 = *(const uint32_t*)(aLo + ao);
            uint32_t al1 = *(const uint32_t*)(aLo + ao + 8 * STRIDE_A);
            uint32_t al2 = *(const uint32_t*)(aLo + ao + 16);
            uint32_t al3 = *(const uint32_t*)(aLo + ao + 8 * STRIDE_A + 16);
#pragma unroll
            for (int in = 0; in < 12; ++in) {
                const uint32_t bo = boff + in * 8 * STRIDE_B + ks * 32;
                uint32_t bh0 = *(const uint32_t*)(bHi + bo);
                uint32_t bh1 = *(const uint32_t*)(bHi + bo + 16);
                uint32_t bl0 = *(const uint32_t*)(bLo + bo);
                uint32_t bl1 = *(const uint32_t*)(bLo + bo + 16);
                mma_bf16(acc[in], ah0, ah1, ah2, ah3, bh0, bh1);
                mma_bf16(acc[in], al0, al1, al2, al3, bh0, bh1);
                mma_bf16(acc[in], ah0, ah1, ah2, ah3, bl0, bl1);
            }
        }

        if (c < 5 && tid >= 128) cp_async_wait0();
        __syncthreads();
    }

    // ---- epilogue: + dstpart, GELU, column sums over this warp's 16 rows ----
    const int sn = wm >> 1;
#pragma unroll
    for (int in = 0; in < 12; ++in) {
        int c = wn * 96 + in * 8 + tg * 2;
        float2 d = *(const float2*)&sDst[sn * HIDDEN + c];
        float t0 = gelu_exact(acc[in][0] + d.x) + gelu_exact(acc[in][2] + d.x);
        float t1 = gelu_exact(acc[in][1] + d.y) + gelu_exact(acc[in][3] + d.y);
#pragma unroll
        for (int off = 4; off < 32; off <<= 1) {
            t0 += __shfl_xor_sync(0xffffffffu, t0, off);
            t1 += __shfl_xor_sync(0xffffffffu, t1, off);
        }
        if (lane < 4) {
            sCol[wm * HIDDEN + c] = t0;
            sCol[wm * HIDDEN + c + 1] = t1;
        }
    }
    __syncthreads();
    for (int i = tid; i < 2 * HIDDEN; i += 256) {
        int s = i / HIDDEN, n = i % HIDDEN;
        g_pooled[(b * 2 + s) * HIDDEN + n] =
            (sCol[s * 2 * HIDDEN + n] + sCol[(s * 2 + 1) * HIDDEN + n]) * (1.0f / 32.0f);
    }
}

// ============================================================
// Kernel C: out = g_pooled @ W2 + b2 via MMA (unchanged from R6)
// ============================================================
__global__ void __launch_bounds__(256, 2)
out_mma_kernel(const float* __restrict__ b2, float* __restrict__ out) {
    __shared__ __align__(16) unsigned char sAhi[64 * STRIDE_A];
    __shared__ __align__(16) unsigned char sAlo[64 * STRIDE_A];
    __shared__ __align__(16) unsigned char sBhi[HIDDEN * STRIDE_B];
    __shared__ __align__(16) unsigned char sBlo[HIDDEN * STRIDE_B];
    __shared__ float sB2[HIDDEN];

    const int tid = threadIdx.x;
    const int lane = tid & 31;
    const int w = tid >> 5;
    const int wm = w & 3, wn = w >> 2;
    const int g = lane >> 2, tg = lane & 3;
    const int s0 = blockIdx.x * 64;

    for (int i = tid; i < HIDDEN; i += 256) sB2[i] = b2[i];

    const int m = tid & 63;
    const int cg = (tid >> 6) & 1;

    float acc[12][4];
#pragma unroll
    for (int i = 0; i < 12; ++i)
#pragma unroll
        for (int j = 0; j < 4; ++j) acc[i][j] = 0.0f;

    const uint32_t aoff = (uint32_t)(wm * 16 + g) * STRIDE_A + tg * 4;
    const uint32_t boff = (uint32_t)(wn * 96 + g) * STRIDE_B + tg * 4;

    for (int ch = 0; ch < 6; ++ch) {
        if (tid < 128) {
            const int jb = cg * 16;
            const float* arow = g_pooled + (s0 + m) * HIDDEN + ch * 32 + jb;
#pragma unroll
            for (int j = 0; j < 16; j += 2) {
                float2 v = *(const float2*)&arow[j];
                __nv_bfloat16 h0 = __float2bfloat16(v.x);
                __nv_bfloat16 h1 = __float2bfloat16(v.y);
                float l0 = v.x - __bfloat162float(h0);
                float l1 = v.y - __bfloat162float(h1);
                __nv_bfloat162 hp; hp.x = h0; hp.y = h1;
                *(uint32_t*)(sAhi + m * STRIDE_A + (jb + j) * 2) =
                    *reinterpret_cast<uint32_t*>(&hp);
                *(uint32_t*)(sAlo + m * STRIDE_A + (jb + j) * 2) = pack_bf16(l0, l1);
            }
        } else {
            const int t2 = tid - 128;
#pragma unroll
            for (int i = 0; i < 12; ++i) {
                int isLo = i >= 6;
                int id = t2 + 128 * (isLo ? (i - 6) : i);
                int n = id >> 2, seg = id & 3;
                const __nv_bfloat16* src =
                    (isLo ? g_W2Tlo : g_W2Thi) + n * HIDDEN + ch * 32 + seg * 8;
                unsigned char* dst = (isLo ? sBlo : sBhi) + n * STRIDE_B + seg * 16;
                *reinterpret_cast<uint4*>(dst) = *reinterpret_cast<const uint4*>(src);
            }
        }
        __syncthreads();

#pragma unroll
        for (int ks = 0; ks < 2; ++ks) {
            const uint32_t ao = aoff + ks * 32;
            uint32_t ah0 = *(const uint32_t*)(sAhi + ao);
            uint32_t ah1 = *(const uint32_t*)(sAhi + ao + 8 * STRIDE_A);
            uint32_t ah2 = *(const uint32_t*)(sAhi + ao + 16);
            uint32_t ah3 = *(const uint32_t*)(sAhi + ao + 8 * STRIDE_A + 16);
            uint32_t al0 = *(const uint32_t*)(sAlo + ao);
            uint32_t al1 = *(const uint32_t*)(sAlo + ao + 8 * STRIDE_A);
            uint32_t al2 = *(const uint32_t*)(sAlo + ao + 16);
            uint32_t al3 = *(const uint32_t*)(sAlo + ao + 8 * STRIDE_A + 16);
#pragma unroll
            for (int in = 0; in < 12; ++in) {
                const uint32_t bo = boff + in * 8 * STRIDE_B + ks * 32;
                uint32_t bh0 = *(const uint32_t*)(sBhi + bo);
                uint32_t bh1 = *(const uint32_t*)(sBhi + bo + 16);
                uint32_t bl0 = *(const uint32_t*)(sBlo + bo);
                uint32_t bl1 = *(const uint32_t*)(sBlo + bo + 16);
                mma_bf16(acc[in], ah0, ah1, ah2, ah3, bh0, bh1);
                mma_bf16(acc[in], al0, al1, al2, al3, bh0, bh1);
                mma_bf16(acc[in], ah0, ah1, ah2, ah3, bl0, bl1);
            }
        }
        __syncthreads();
    }

    const int r_hi = s0 + wm * 16 + g;
#pragma unroll
    for (int in = 0; in < 12; ++in) {
        int c = wn * 96 + in * 8 + tg * 2;
        float2 bb = *(const float2*)&sB2[c];
        float2 v0 = {acc[in][0] + bb.x, acc[in][1] + bb.y};
        float2 v1 = {acc[in][2] + bb.x, acc[in][3] + bb.y};
        *(float2*)&out[r_hi * HIDDEN + c] = v0;
        *(float2*)&out[(r_hi + 8) * HIDDEN + c] = v1;
    }
}

// ============================================================
extern "C" void kernel_launch(void* const* d_in, const int* in_sizes, int n_in,
                              void* d_out, int out_size) {
    const float* feat = (const float*)d_in[0];
    const float* pos = (const float*)d_in[1];
    const int* src_idx = (const int*)d_in[2];
    const int* dst_idx = (const int*)d_in[3];
    const float* Win = (const float*)d_in[4];
    const float* bin = (const float*)d_in[5];
    const float* W1 = (const float*)d_in[6];
    const float* b1 = (const float*)d_in[7];
    const float* W2 = (const float*)d_in[8];
    const float* b2 = (const float*)d_in[9];
    float* out = (float*)d_out;

    const int E = in_sizes[2];
    const int S = E / MAXDEG;   // 8192

    static int smem_set = 0;
    if (!smem_set) {
        cudaFuncSetAttribute(snp_mma_kernel, cudaFuncAttributeMaxDynamicSharedMemorySize,
                             SMEMB_TOTAL);
        smem_set = 1;
    }

    weight_split_kernel<<<(HIDDEN * HIDDEN + 255) / 256, 256>>>(W1, W2);
    dst_mma_kernel<<<S / 64, 256>>>(feat, pos, dst_idx, Win, bin, b1);
    snp_mma_kernel<<<S / 2, 256, SMEMB_TOTAL>>>(feat, pos, src_idx, Win, bin);
    out_mma_kernel<<<S / 64, 256>>>(b2, out);
}

// round 8
// speedup vs baseline: 2.3612x; 1.0129x over previous
#include <cuda_runtime.h>
#include <cuda_bf16.h>
#include <cstdint>

#define HIDDEN 192
#define MAXDEG 32
#define MAX_S 8192

// scratch (device globals: allocation-free). 16B-aligned for vector ld/st + cp.async.
__device__ __align__(16) float g_dstpart[MAX_S * HIDDEN];         // b1 + x_dst @ W1_bot
__device__ __align__(16) float g_pooled[MAX_S * HIDDEN];          // mean(gelu(...))
__device__ __align__(16) __nv_bfloat16 g_W1Thi[HIDDEN * HIDDEN];  // W1_top^T hi [n][k]
__device__ __align__(16) __nv_bfloat16 g_W1Tlo[HIDDEN * HIDDEN];  // W1_top^T lo
__device__ __align__(16) __nv_bfloat16 g_W1bThi[HIDDEN * HIDDEN]; // W1_bot^T hi
__device__ __align__(16) __nv_bfloat16 g_W1bTlo[HIDDEN * HIDDEN]; // W1_bot^T lo
__device__ __align__(16) __nv_bfloat16 g_W2Thi[HIDDEN * HIDDEN];  // W2^T hi
__device__ __align__(16) __nv_bfloat16 g_W2Tlo[HIDDEN * HIDDEN];  // W2^T lo

// ---------------- helpers ----------------
__device__ __forceinline__ float sin_poly(float x) {
    float x2 = x * x;
    float p = -1.98412698e-4f;
    p = fmaf(p, x2, 8.33333333e-3f);
    p = fmaf(p, x2, -1.66666667e-1f);
    return fmaf(x * x2, p, x);
}
__device__ __forceinline__ float cos_poly(float x) {
    float x2 = x * x;
    float p = 2.48015873e-5f;
    p = fmaf(p, x2, -1.38888889e-3f);
    p = fmaf(p, x2, 4.16666667e-2f);
    p = fmaf(p, x2, -0.5f);
    return fmaf(p, x2, 1.0f);
}
__device__ __forceinline__ float gelu_exact(float x) {
    return 0.5f * x * (1.0f + erff(x * 0.7071067811865476f));
}
__device__ __forceinline__ float embed_channel(int c, float f0, float f1, float f2,
                                               const float* pp, const float* sWin,
                                               const float* sBin, const float* sOmega) {
    float v = sBin[c];
    v = fmaf(f0, sWin[c], v);
    v = fmaf(f1, sWin[HIDDEN + c], v);
    v = fmaf(f2, sWin[2 * HIDDEN + c], v);
    int axis = c >> 6;
    int j = c & 63;
    float ang = pp[axis] * sOmega[j & 31];
    float e = (j < 32) ? sin_poly(ang) : cos_poly(ang);
    return v + e;
}
__device__ __forceinline__ void mma_bf16(float* c, uint32_t a0, uint32_t a1, uint32_t a2,
                                         uint32_t a3, uint32_t b0, uint32_t b1) {
    asm volatile(
        "mma.sync.aligned.m16n8k16.row.col.f32.bf16.bf16.f32 "
        "{%0,%1,%2,%3}, {%4,%5,%6,%7}, {%8,%9}, {%0,%1,%2,%3};"
        : "+f"(c[0]), "+f"(c[1]), "+f"(c[2]), "+f"(c[3])
        : "r"(a0), "r"(a1), "r"(a2), "r"(a3), "r"(b0), "r"(b1));
}
__device__ __forceinline__ void ldsm_x4(uint32_t& r0, uint32_t& r1, uint32_t& r2,
                                        uint32_t& r3, uint32_t addr) {
    asm volatile("ldmatrix.sync.aligned.m8n8.x4.shared.b16 {%0,%1,%2,%3}, [%4];"
                 : "=r"(r0), "=r"(r1), "=r"(r2), "=r"(r3) : "r"(addr));
}
__device__ __forceinline__ uint32_t pack_bf16(float v0, float v1) {
    __nv_bfloat162 t;
    t.x = __float2bfloat16(v0);
    t.y = __float2bfloat16(v1);
    return *reinterpret_cast<uint32_t*>(&t);
}
__device__ __forceinline__ uint32_t smem_u32(const void* p) {
    uint32_t a;
    asm("{ .reg .u64 t; cvta.to.shared.u64 t, %1; cvt.u32.u64 %0, t; }" : "=r"(a) : "l"(p));
    return a;
}
__device__ __forceinline__ void cp_async16(void* dst_smem, const void* src) {
    uint32_t d = smem_u32(dst_smem);
    asm volatile("cp.async.cg.shared.global [%0], [%1], 16;" :: "r"(d), "l"(src) : "memory");
}
__device__ __forceinline__ void cp_async_commit() {
    asm volatile("cp.async.commit_group;" ::: "memory");
}
__device__ __forceinline__ void cp_async_wait0() {
    asm volatile("cp.async.wait_group 0;" ::: "memory");
}

#define STRIDE_A 72  // 32 bf16 (64B) + 8B pad
#define STRIDE_B 80  // 32 bf16 (64B) + 16B pad; LDSM-conflict-free (banks 20r mod 32)

// B-fragment lane offset for ldmatrix.x4 (pair p covers atoms 2p, 2p+1):
//  lanes 0-7: atom2p rows, k-lo | 8-15: atom2p rows, k-hi | 16-23: atom2p+1, k-lo | 24-31: k-hi
__device__ __forceinline__ uint32_t b_lane_off(int wn, int lane) {
    return (uint32_t)(wn * 96 + ((lane >> 4) & 1) * 8 + (lane & 7)) * STRIDE_B +
           ((lane >> 3) & 1) * 16;
}

// shared consume step: 2 ks x 6 pairs, A via LDS, B via LDSM.x4, 3-term bf16
#define CONSUME_CHUNK(aHi, aLo, bHiA, bLoA)                                              \
    _Pragma("unroll") for (int ks = 0; ks < 2; ++ks) {                                   \
        const uint32_t ao = aoff + ks * 32;                                              \
        uint32_t ah0 = *(const uint32_t*)((aHi) + ao);                                   \
        uint32_t ah1 = *(const uint32_t*)((aHi) + ao + 8 * STRIDE_A);                    \
        uint32_t ah2 = *(const uint32_t*)((aHi) + ao + 16);                              \
        uint32_t ah3 = *(const uint32_t*)((aHi) + ao + 8 * STRIDE_A + 16);               \
        uint32_t al0 = *(const uint32_t*)((aLo) + ao);                                   \
        uint32_t al1 = *(const uint32_t*)((aLo) + ao + 8 * STRIDE_A);                    \
        uint32_t al2 = *(const uint32_t*)((aLo) + ao + 16);                              \
        uint32_t al3 = *(const uint32_t*)((aLo) + ao + 8 * STRIDE_A + 16);               \
        _Pragma("unroll") for (int p = 0; p < 6; ++p) {                                  \
            uint32_t bh0, bh1, bh2, bh3, bl0, bl1, bl2, bl3;                             \
            ldsm_x4(bh0, bh1, bh2, bh3, (bHiA) + p * (16 * STRIDE_B) + ks * 32);         \
            ldsm_x4(bl0, bl1, bl2, bl3, (bLoA) + p * (16 * STRIDE_B) + ks * 32);         \
            mma_bf16(acc[2 * p], ah0, ah1, ah2, ah3, bh0, bh1);                          \
            mma_bf16(acc[2 * p], al0, al1, al2, al3, bh0, bh1);                          \
            mma_bf16(acc[2 * p], ah0, ah1, ah2, ah3, bl0, bl1);                          \
            mma_bf16(acc[2 * p + 1], ah0, ah1, ah2, ah3, bh2, bh3);                      \
            mma_bf16(acc[2 * p + 1], al0, al1, al2, al3, bh2, bh3);                      \
            mma_bf16(acc[2 * p + 1], ah0, ah1, ah2, ah3, bl2, bl3);                      \
        }                                                                                \
    }

// ============================================================
// Kernel P: split W1_top^T, W1_bot^T, W2^T into bf16 hi/lo
// ============================================================
__global__ void __launch_bounds__(256)
weight_split_kernel(const float* __restrict__ W1, const float* __restrict__ W2) {
    int i = blockIdx.x * 256 + threadIdx.x;
    if (i >= HIDDEN * HIDDEN) return;
    int k = i / HIDDEN, n = i % HIDDEN;
    {
        float w = W1[k * HIDDEN + n];
        __nv_bfloat16 hi = __float2bfloat16(w);
        g_W1Thi[n * HIDDEN + k] = hi;
        g_W1Tlo[n * HIDDEN + k] = __float2bfloat16(w - __bfloat162float(hi));
    }
    {
        float w = W1[(HIDDEN + k) * HIDDEN + n];
        __nv_bfloat16 hi = __float2bfloat16(w);
        g_W1bThi[n * HIDDEN + k] = hi;
        g_W1bTlo[n * HIDDEN + k] = __float2bfloat16(w - __bfloat162float(hi));
    }
    {
        float w = W2[k * HIDDEN + n];
        __nv_bfloat16 hi = __float2bfloat16(w);
        g_W2Thi[n * HIDDEN + k] = hi;
        g_W2Tlo[n * HIDDEN + k] = __float2bfloat16(w - __bfloat162float(hi));
    }
}

// ============================================================
// Kernel A: dst partial via MMA. CTA = 64 supernodes (M=64).
// ============================================================
__global__ void __launch_bounds__(256, 2)
dst_mma_kernel(const float* __restrict__ feat, const float* __restrict__ pos,
               const int* __restrict__ dst_idx, const float* __restrict__ Win,
               const float* __restrict__ bin, const float* __restrict__ b1) {
    __shared__ __align__(16) unsigned char sAhi[64 * STRIDE_A];
    __shared__ __align__(16) unsigned char sAlo[64 * STRIDE_A];
    __shared__ __align__(16) unsigned char sBhi[HIDDEN * STRIDE_B];
    __shared__ __align__(16) unsigned char sBlo[HIDDEN * STRIDE_B];
    __shared__ float sWin[3 * HIDDEN], sBin[HIDDEN], sOmega[32], sB1[HIDDEN];

    const int tid = threadIdx.x;
    const int lane = tid & 31;
    const int w = tid >> 5;
    const int wm = w & 3, wn = w >> 2;
    const int g = lane >> 2, tg = lane & 3;
    const int s0 = blockIdx.x * 64;

    for (int i = tid; i < 3 * HIDDEN; i += 256) sWin[i] = Win[i];
    for (int i = tid; i < HIDDEN; i += 256) sBin[i] = bin[i];
    for (int i = tid; i < HIDDEN; i += 256) sB1[i] = b1[i];
    if (tid < 32) sOmega[tid] = exp2f(-(float)tid * 0.4152410118609203f);

    float f0 = 0.f, f1 = 0.f, f2 = 0.f, pp[3] = {0.f, 0.f, 0.f};
    const int m = tid & 63;
    const int cg = (tid >> 6) & 1;
    if (tid < 128) {
        int node = dst_idx[(s0 + m) * MAXDEG];
        f0 = feat[node * 3]; f1 = feat[node * 3 + 1]; f2 = feat[node * 3 + 2];
        pp[0] = pos[node * 3]; pp[1] = pos[node * 3 + 1]; pp[2] = pos[node * 3 + 2];
    }
    __syncthreads();

    float acc[12][4];
#pragma unroll
    for (int i = 0; i < 12; ++i)
#pragma unroll
        for (int j = 0; j < 4; ++j) acc[i][j] = 0.0f;

    const uint32_t aoff = (uint32_t)(wm * 16 + g) * STRIDE_A + tg * 4;
    const uint32_t bHiA = smem_u32(sBhi) + b_lane_off(wn, lane);
    const uint32_t bLoA = smem_u32(sBlo) + b_lane_off(wn, lane);

    for (int ch = 0; ch < 6; ++ch) {
        if (tid < 128) {
            const int jb = cg * 16;
#pragma unroll
            for (int j = 0; j < 16; j += 2) {
                int c0 = ch * 32 + jb + j;
                float v0 = embed_channel(c0, f0, f1, f2, pp, sWin, sBin, sOmega);
                float v1 = embed_channel(c0 + 1, f0, f1, f2, pp, sWin, sBin, sOmega);
                __nv_bfloat16 h0 = __float2bfloat16(v0);
                __nv_bfloat16 h1 = __float2bfloat16(v1);
                float l0 = v0 - __bfloat162float(h0);
                float l1 = v1 - __bfloat162float(h1);
                __nv_bfloat162 hp; hp.x = h0; hp.y = h1;
                *(uint32_t*)(sAhi + m * STRIDE_A + (jb + j) * 2) =
                    *reinterpret_cast<uint32_t*>(&hp);
                *(uint32_t*)(sAlo + m * STRIDE_A + (jb + j) * 2) = pack_bf16(l0, l1);
            }
        } else {
            const int t2 = tid - 128;
#pragma unroll
            for (int i = 0; i < 12; ++i) {
                int isLo = i >= 6;
                int id = t2 + 128 * (isLo ? (i - 6) : i);
                int n = id >> 2, seg = id & 3;
                const __nv_bfloat16* src =
                    (isLo ? g_W1bTlo : g_W1bThi) + n * HIDDEN + ch * 32 + seg * 8;
                unsigned char* dst = (isLo ? sBlo : sBhi) + n * STRIDE_B + seg * 16;
                *reinterpret_cast<uint4*>(dst) = *reinterpret_cast<const uint4*>(src);
            }
        }
        __syncthreads();
        CONSUME_CHUNK(sAhi, sAlo, bHiA, bLoA)
        __syncthreads();
    }

    const int r_hi = s0 + wm * 16 + g;
#pragma unroll
    for (int in = 0; in < 12; ++in) {
        int c = wn * 96 + in * 8 + tg * 2;
        float2 bb = *(const float2*)&sB1[c];
        float2 v0 = {acc[in][0] + bb.x, acc[in][1] + bb.y};
        float2 v1 = {acc[in][2] + bb.x, acc[in][3] + bb.y};
        *(float2*)&g_dstpart[r_hi * HIDDEN + c] = v0;
        *(float2*)&g_dstpart[(r_hi + 8) * HIDDEN + c] = v1;
    }
}

// ============================================================
// Kernel B: pipelined snp_mma — double buffer, 1 sync/chunk,
// cp.async B moves + LDSM fragment loads. Dynamic smem (~87KB).
// ============================================================
#define AB (64 * STRIDE_A)        // 4608
#define BBUF (HIDDEN * STRIDE_B)  // 15360
#define OFF_AHI 0
#define OFF_ALO (2 * AB)
#define OFF_BHI (4 * AB)
#define OFF_BLO (4 * AB + 2 * BBUF)
#define OFF_WIN (4 * AB + 4 * BBUF)
#define OFF_BIN (OFF_WIN + 3 * HIDDEN * 4)
#define OFF_OMG (OFF_BIN + HIDDEN * 4)
#define OFF_DST (OFF_OMG + 128)
#define OFF_COL (OFF_DST + 2 * HIDDEN * 4)
#define SMEMB_TOTAL (OFF_COL + 4 * HIDDEN * 4)   // 86912

__device__ __forceinline__ void produce_A(unsigned char* aHi, unsigned char* aLo, int ch,
                                          int m, int jb, float f0, float f1, float f2,
                                          const float* pp, const float* sWin,
                                          const float* sBin, const float* sOmega) {
#pragma unroll
    for (int j = 0; j < 16; j += 2) {
        int c0 = ch * 32 + jb + j;
        float v0 = embed_channel(c0, f0, f1, f2, pp, sWin, sBin, sOmega);
        float v1 = embed_channel(c0 + 1, f0, f1, f2, pp, sWin, sBin, sOmega);
        __nv_bfloat16 h0 = __float2bfloat16(v0);
        __nv_bfloat16 h1 = __float2bfloat16(v1);
        float l0 = v0 - __bfloat162float(h0);
        float l1 = v1 - __bfloat162float(h1);
        __nv_bfloat162 hp; hp.x = h0; hp.y = h1;
        *(uint32_t*)(aHi + m * STRIDE_A + (jb + j) * 2) = *reinterpret_cast<uint32_t*>(&hp);
        *(uint32_t*)(aLo + m * STRIDE_A + (jb + j) * 2) = pack_bf16(l0, l1);
    }
}

__device__ __forceinline__ void copy_B_async(unsigned char* bHi, unsigned char* bLo,
                                             int ch, int t2) {
#pragma unroll
    for (int i = 0; i < 12; ++i) {
        int isLo = i >= 6;
        int id = t2 + 128 * (isLo ? (i - 6) : i);   // 0..767
        int n = id >> 2, seg = id & 3;
        const __nv_bfloat16* src =
            (isLo ? g_W1Tlo : g_W1Thi) + n * HIDDEN + ch * 32 + seg * 8;
        unsigned char* dst = (isLo ? bLo : bHi) + n * STRIDE_B + seg * 16;
        cp_async16(dst, src);
    }
}

__global__ void __launch_bounds__(256, 2)
snp_mma_kernel(const float* __restrict__ feat, const float* __restrict__ pos,
               const int* __restrict__ src_idx, const float* __restrict__ Win,
               const float* __restrict__ bin) {
    extern __shared__ __align__(16) unsigned char sm[];
    float* sWin = (float*)(sm + OFF_WIN);
    float* sBin = (float*)(sm + OFF_BIN);
    float* sOmega = (float*)(sm + OFF_OMG);
    float* sDst = (float*)(sm + OFF_DST);
    float* sCol = (float*)(sm + OFF_COL);   // [4][HIDDEN]

    const int b = blockIdx.x;
    const int tid = threadIdx.x;
    const int lane = tid & 31;
    const int w = tid >> 5;
    const int wm = w & 3, wn = w >> 2;
    const int g = lane >> 2, tg = lane & 3;

    for (int i = tid; i < 3 * HIDDEN; i += 256) sWin[i] = Win[i];
    for (int i = tid; i < HIDDEN; i += 256) sBin[i] = bin[i];
    for (int i = tid; i < 2 * HIDDEN; i += 256) sDst[i] = g_dstpart[b * 2 * HIDDEN + i];
    if (tid < 32) sOmega[tid] = exp2f(-(float)tid * 0.4152410118609203f);

    float f0 = 0.f, f1 = 0.f, f2 = 0.f, pp[3] = {0.f, 0.f, 0.f};
    const int m = tid & 63;
    const int jb = ((tid >> 6) & 1) * 16;
    if (tid < 128) {
        int node = src_idx[b * 64 + m];
        f0 = feat[node * 3]; f1 = feat[node * 3 + 1]; f2 = feat[node * 3 + 2];
        pp[0] = pos[node * 3]; pp[1] = pos[node * 3 + 1]; pp[2] = pos[node * 3 + 2];
    }
    const int t2 = tid - 128;
    __syncthreads();

    float acc[12][4];
#pragma unroll
    for (int i = 0; i < 12; ++i)
#pragma unroll
        for (int j = 0; j < 4; ++j) acc[i][j] = 0.0f;

    const uint32_t aoff = (uint32_t)(wm * 16 + g) * STRIDE_A + tg * 4;
    const uint32_t smB = smem_u32(sm);
    const uint32_t bLane = b_lane_off(wn, lane);

    // ---- prologue: fill buffer 0 with chunk 0 ----
    if (tid < 128) {
        produce_A(sm + OFF_AHI, sm + OFF_ALO, 0, m, jb, f0, f1, f2, pp, sWin, sBin, sOmega);
    } else {
        copy_B_async(sm + OFF_BHI, sm + OFF_BLO, 0, t2);
        cp_async_commit();
        cp_async_wait0();
    }
    __syncthreads();

    // ---- pipelined main loop ----
    for (int c = 0; c < 6; ++c) {
        const int cur = c & 1;
        const int nxt = (c + 1) & 1;
        if (c < 5) {
            if (tid < 128) {
                produce_A(sm + OFF_AHI + nxt * AB, sm + OFF_ALO + nxt * AB, c + 1, m, jb,
                          f0, f1, f2, pp, sWin, sBin, sOmega);
            } else {
                copy_B_async(sm + OFF_BHI + nxt * BBUF, sm + OFF_BLO + nxt * BBUF, c + 1, t2);
                cp_async_commit();
            }
        }

        const unsigned char* aHi = sm + OFF_AHI + cur * AB;
        const unsigned char* aLo = sm + OFF_ALO + cur * AB;
        const uint32_t bHiA = smB + OFF_BHI + cur * BBUF + bLane;
        const uint32_t bLoA = smB + OFF_BLO + cur * BBUF + bLane;
        CONSUME_CHUNK(aHi, aLo, bHiA, bLoA)

        if (c < 5 && tid >= 128) cp_async_wait0();
        __syncthreads();
    }

    // ---- epilogue: + dstpart, GELU, column sums over this warp's 16 rows ----
    const int sn = wm >> 1;
#pragma unroll
    for (int in = 0; in < 12; ++in) {
        int c = wn * 96 + in * 8 + tg * 2;
        float2 d = *(const float2*)&sDst[sn * HIDDEN + c];
        float t0 = gelu_exact(acc[in][0] + d.x) + gelu_exact(acc[in][2] + d.x);
        float t1 = gelu_exact(acc[in][1] + d.y) + gelu_exact(acc[in][3] + d.y);
#pragma unroll
        for (int off = 4; off < 32; off <<= 1) {
            t0 += __shfl_xor_sync(0xffffffffu, t0, off);
            t1 += __shfl_xor_sync(0xffffffffu, t1, off);
        }
        if (lane < 4) {
            sCol[wm * HIDDEN + c] = t0;
            sCol[wm * HIDDEN + c + 1] = t1;
        }
    }
    __syncthreads();
    for (int i = tid; i < 2 * HIDDEN; i += 256) {
        int s = i / HIDDEN, n = i % HIDDEN;
        g_pooled[(b * 2 + s) * HIDDEN + n] =
            (sCol[s * 2 * HIDDEN + n] + sCol[(s * 2 + 1) * HIDDEN + n]) * (1.0f / 32.0f);
    }
}

// ============================================================
// Kernel C: out = g_pooled @ W2 + b2 via MMA. CTA = 64 rows.
// ============================================================
__global__ void __launch_bounds__(256, 2)
out_mma_kernel(const float* __restrict__ b2, float* __restrict__ out) {
    __shared__ __align__(16) unsigned char sAhi[64 * STRIDE_A];
    __shared__ __align__(16) unsigned char sAlo[64 * STRIDE_A];
    __shared__ __align__(16) unsigned char sBhi[HIDDEN * STRIDE_B];
    __shared__ __align__(16) unsigned char sBlo[HIDDEN * STRIDE_B];
    __shared__ float sB2[HIDDEN];

    const int tid = threadIdx.x;
    const int lane = tid & 31;
    const int w = tid >> 5;
    const int wm = w & 3, wn = w >> 2;
    const int g = lane >> 2, tg = lane & 3;
    const int s0 = blockIdx.x * 64;

    for (int i = tid; i < HIDDEN; i += 256) sB2[i] = b2[i];

    const int m = tid & 63;
    const int cg = (tid >> 6) & 1;

    float acc[12][4];
#pragma unroll
    for (int i = 0; i < 12; ++i)
#pragma unroll
        for (int j = 0; j < 4; ++j) acc[i][j] = 0.0f;

    const uint32_t aoff = (uint32_t)(wm * 16 + g) * STRIDE_A + tg * 4;
    const uint32_t bHiA = smem_u32(sBhi) + b_lane_off(wn, lane);
    const uint32_t bLoA = smem_u32(sBlo) + b_lane_off(wn, lane);

    for (int ch = 0; ch < 6; ++ch) {
        if (tid < 128) {
            const int jb = cg * 16;
            const float* arow = g_pooled + (s0 + m) * HIDDEN + ch * 32 + jb;
#pragma unroll
            for (int j = 0; j < 16; j += 2) {
                float2 v = *(const float2*)&arow[j];
                __nv_bfloat16 h0 = __float2bfloat16(v.x);
                __nv_bfloat16 h1 = __float2bfloat16(v.y);
                float l0 = v.x - __bfloat162float(h0);
                float l1 = v.y - __bfloat162float(h1);
                __nv_bfloat162 hp; hp.x = h0; hp.y = h1;
                *(uint32_t*)(sAhi + m * STRIDE_A + (jb + j) * 2) =
                    *reinterpret_cast<uint32_t*>(&hp);
                *(uint32_t*)(sAlo + m * STRIDE_A + (jb + j) * 2) = pack_bf16(l0, l1);
            }
        } else {
            const int t2 = tid - 128;
#pragma unroll
            for (int i = 0; i < 12; ++i) {
                int isLo = i >= 6;
                int id = t2 + 128 * (isLo ? (i - 6) : i);
                int n = id >> 2, seg = id & 3;
                const __nv_bfloat16* src =
                    (isLo ? g_W2Tlo : g_W2Thi) + n * HIDDEN + ch * 32 + seg * 8;
                unsigned char* dst = (isLo ? sBlo : sBhi) + n * STRIDE_B + seg * 16;
                *reinterpret_cast<uint4*>(dst) = *reinterpret_cast<const uint4*>(src);
            }
        }
        __syncthreads();
        CONSUME_CHUNK(sAhi, sAlo, bHiA, bLoA)
        __syncthreads();
    }

    const int r_hi = s0 + wm * 16 + g;
#pragma unroll
    for (int in = 0; in < 12; ++in) {
        int c = wn * 96 + in * 8 + tg * 2;
        float2 bb = *(const float2*)&sB2[c];
        float2 v0 = {acc[in][0] + bb.x, acc[in][1] + bb.y};
        float2 v1 = {acc[in][2] + bb.x, acc[in][3] + bb.y};
        *(float2*)&out[r_hi * HIDDEN + c] = v0;
        *(float2*)&out[(r_hi + 8) * HIDDEN + c] = v1;
    }
}

// ============================================================
extern "C" void kernel_launch(void* const* d_in, const int* in_sizes, int n_in,
                              void* d_out, int out_size) {
    const float* feat = (const float*)d_in[0];
    const float* pos = (const float*)d_in[1];
    const int* src_idx = (const int*)d_in[2];
    const int* dst_idx = (const int*)d_in[3];
    const float* Win = (const float*)d_in[4];
    const float* bin = (const float*)d_in[5];
    const float* W1 = (const float*)d_in[6];
    const float* b1 = (const float*)d_in[7];
    const float* W2 = (const float*)d_in[8];
    const float* b2 = (const float*)d_in[9];
    float* out = (float*)d_out;

    const int E = in_sizes[2];
    const int S = E / MAXDEG;   // 8192

    static int smem_set = 0;
    if (!smem_set) {
        cudaFuncSetAttribute(snp_mma_kernel, cudaFuncAttributeMaxDynamicSharedMemorySize,
                             SMEMB_TOTAL);
        smem_set = 1;
    }

    weight_split_kernel<<<(HIDDEN * HIDDEN + 255) / 256, 256>>>(W1, W2);
    dst_mma_kernel<<<S / 64, 256>>>(feat, pos, dst_idx, Win, bin, b1);
    snp_mma_kernel<<<S / 2, 256, SMEMB_TOTAL>>>(feat, pos, src_idx, Win, bin);
    out_mma_kernel<<<S / 64, 256>>>(b2, out);
}

// round 9
// speedup vs baseline: 2.8331x; 1.1999x over previous
#include <cuda_runtime.h>
#include <cuda_bf16.h>
#include <cuda_fp16.h>
#include <cstdint>

#define HIDDEN 192
#define MAXDEG 32
#define MAX_S 8192

// scratch (device globals: allocation-free). 16B-aligned for vector ld/st + cp.async.
__device__ __align__(16) float g_dstpart[MAX_S * HIDDEN];         // b1 + x_dst @ W1_bot
__device__ __align__(16) float g_pooled[MAX_S * HIDDEN];          // mean(gelu(...))
__device__ __align__(16) __half g_W1Tf16[HIDDEN * HIDDEN];        // W1_top^T fp16 [n][k]
__device__ __align__(16) __nv_bfloat16 g_W1bThi[HIDDEN * HIDDEN]; // W1_bot^T hi
__device__ __align__(16) __nv_bfloat16 g_W1bTlo[HIDDEN * HIDDEN]; // W1_bot^T lo
__device__ __align__(16) __nv_bfloat16 g_W2Thi[HIDDEN * HIDDEN];  // W2^T hi
__device__ __align__(16) __nv_bfloat16 g_W2Tlo[HIDDEN * HIDDEN];  // W2^T lo

// ---------------- helpers ----------------
__device__ __forceinline__ float sin_poly(float x) {
    float x2 = x * x;
    float p = -1.98412698e-4f;
    p = fmaf(p, x2, 8.33333333e-3f);
    p = fmaf(p, x2, -1.66666667e-1f);
    return fmaf(x * x2, p, x);
}
__device__ __forceinline__ float cos_poly(float x) {
    float x2 = x * x;
    float p = 2.48015873e-5f;
    p = fmaf(p, x2, -1.38888889e-3f);
    p = fmaf(p, x2, 4.16666667e-2f);
    p = fmaf(p, x2, -0.5f);
    return fmaf(p, x2, 1.0f);
}
__device__ __forceinline__ float gelu_exact(float x) {
    return 0.5f * x * (1.0f + erff(x * 0.7071067811865476f));
}
__device__ __forceinline__ float embed_channel(int c, float f0, float f1, float f2,
                                               const float* pp, const float* sWin,
                                               const float* sBin, const float* sOmega) {
    float v = sBin[c];
    v = fmaf(f0, sWin[c], v);
    v = fmaf(f1, sWin[HIDDEN + c], v);
    v = fmaf(f2, sWin[2 * HIDDEN + c], v);
    int axis = c >> 6;
    int j = c & 63;
    float ang = pp[axis] * sOmega[j & 31];
    float e = (j < 32) ? sin_poly(ang) : cos_poly(ang);
    return v + e;
}
__device__ __forceinline__ void mma_bf16(float* c, uint32_t a0, uint32_t a1, uint32_t a2,
                                         uint32_t a3, uint32_t b0, uint32_t b1) {
    asm volatile(
        "mma.sync.aligned.m16n8k16.row.col.f32.bf16.bf16.f32 "
        "{%0,%1,%2,%3}, {%4,%5,%6,%7}, {%8,%9}, {%0,%1,%2,%3};"
        : "+f"(c[0]), "+f"(c[1]), "+f"(c[2]), "+f"(c[3])
        : "r"(a0), "r"(a1), "r"(a2), "r"(a3), "r"(b0), "r"(b1));
}
__device__ __forceinline__ void mma_f16(float* c, uint32_t a0, uint32_t a1, uint32_t a2,
                                        uint32_t a3, uint32_t b0, uint32_t b1) {
    asm volatile(
        "mma.sync.aligned.m16n8k16.row.col.f32.f16.f16.f32 "
        "{%0,%1,%2,%3}, {%4,%5,%6,%7}, {%8,%9}, {%0,%1,%2,%3};"
        : "+f"(c[0]), "+f"(c[1]), "+f"(c[2]), "+f"(c[3])
        : "r"(a0), "r"(a1), "r"(a2), "r"(a3), "r"(b0), "r"(b1));
}
__device__ __forceinline__ void ldsm_x4(uint32_t& r0, uint32_t& r1, uint32_t& r2,
                                        uint32_t& r3, uint32_t addr) {
    asm volatile("ldmatrix.sync.aligned.m8n8.x4.shared.b16 {%0,%1,%2,%3}, [%4];"
                 : "=r"(r0), "=r"(r1), "=r"(r2), "=r"(r3) : "r"(addr));
}
__device__ __forceinline__ uint32_t pack_bf16(float v0, float v1) {
    __nv_bfloat162 t;
    t.x = __float2bfloat16(v0);
    t.y = __float2bfloat16(v1);
    return *reinterpret_cast<uint32_t*>(&t);
}
__device__ __forceinline__ uint32_t pack_f16(float v0, float v1) {
    __half2 t;
    t.x = __float2half_rn(v0);
    t.y = __float2half_rn(v1);
    return *reinterpret_cast<uint32_t*>(&t);
}
__device__ __forceinline__ uint32_t smem_u32(const void* p) {
    uint32_t a;
    asm("{ .reg .u64 t; cvta.to.shared.u64 t, %1; cvt.u32.u64 %0, t; }" : "=r"(a) : "l"(p));
    return a;
}
__device__ __forceinline__ void cp_async16(void* dst_smem, const void* src) {
    uint32_t d = smem_u32(dst_smem);
    asm volatile("cp.async.cg.shared.global [%0], [%1], 16;" :: "r"(d), "l"(src) : "memory");
}
__device__ __forceinline__ void cp_async_commit() {
    asm volatile("cp.async.commit_group;" ::: "memory");
}
__device__ __forceinline__ void cp_async_wait0() {
    asm volatile("cp.async.wait_group 0;" ::: "memory");
}

#define STRIDE_A 72  // 32 x b16 (64B) + 8B pad
#define STRIDE_B 80  // 32 x b16 (64B) + 16B pad; LDSM-conflict-free

// B-fragment lane offset for ldmatrix.x4 (pair p covers atoms 2p, 2p+1)
__device__ __forceinline__ uint32_t b_lane_off(int wn, int lane) {
    return (uint32_t)(wn * 96 + ((lane >> 4) & 1) * 8 + (lane & 7)) * STRIDE_B +
           ((lane >> 3) & 1) * 16;
}

// bf16 3-term consume (dst/out kernels)
#define CONSUME_CHUNK(aHi, aLo, bHiA, bLoA)                                              \
    _Pragma("unroll") for (int ks = 0; ks < 2; ++ks) {                                   \
        const uint32_t ao = aoff + ks * 32;                                              \
        uint32_t ah0 = *(const uint32_t*)((aHi) + ao);                                   \
        uint32_t ah1 = *(const uint32_t*)((aHi) + ao + 8 * STRIDE_A);                    \
        uint32_t ah2 = *(const uint32_t*)((aHi) + ao + 16);                              \
        uint32_t ah3 = *(const uint32_t*)((aHi) + ao + 8 * STRIDE_A + 16);               \
        uint32_t al0 = *(const uint32_t*)((aLo) + ao);                                   \
        uint32_t al1 = *(const uint32_t*)((aLo) + ao + 8 * STRIDE_A);                    \
        uint32_t al2 = *(const uint32_t*)((aLo) + ao + 16);                              \
        uint32_t al3 = *(const uint32_t*)((aLo) + ao + 8 * STRIDE_A + 16);               \
        _Pragma("unroll") for (int p = 0; p < 6; ++p) {                                  \
            uint32_t bh0, bh1, bh2, bh3, bl0, bl1, bl2, bl3;                             \
            ldsm_x4(bh0, bh1, bh2, bh3, (bHiA) + p * (16 * STRIDE_B) + ks * 32);         \
            ldsm_x4(bl0, bl1, bl2, bl3, (bLoA) + p * (16 * STRIDE_B) + ks * 32);         \
            mma_bf16(acc[2 * p], ah0, ah1, ah2, ah3, bh0, bh1);                          \
            mma_bf16(acc[2 * p], al0, al1, al2, al3, bh0, bh1);                          \
            mma_bf16(acc[2 * p], ah0, ah1, ah2, ah3, bl0, bl1);                          \
            mma_bf16(acc[2 * p + 1], ah0, ah1, ah2, ah3, bh2, bh3);                      \
            mma_bf16(acc[2 * p + 1], al0, al1, al2, al3, bh2, bh3);                      \
            mma_bf16(acc[2 * p + 1], ah0, ah1, ah2, ah3, bl2, bl3);                      \
        }                                                                                \
    }

// fp16 2-term consume (snp): A split hi/lo, B plain fp16
#define CONSUME_CHUNK_F16(aHi, aLo, bHiA)                                                \
    _Pragma("unroll") for (int ks = 0; ks < 2; ++ks) {                                   \
        const uint32_t ao = aoff + ks * 32;                                              \
        uint32_t ah0 = *(const uint32_t*)((aHi) + ao);                                   \
        uint32_t ah1 = *(const uint32_t*)((aHi) + ao + 8 * STRIDE_A);                    \
        uint32_t ah2 = *(const uint32_t*)((aHi) + ao + 16);                              \
        uint32_t ah3 = *(const uint32_t*)((aHi) + ao + 8 * STRIDE_A + 16);               \
        uint32_t al0 = *(const uint32_t*)((aLo) + ao);                                   \
        uint32_t al1 = *(const uint32_t*)((aLo) + ao + 8 * STRIDE_A);                    \
        uint32_t al2 = *(const uint32_t*)((aLo) + ao + 16);                              \
        uint32_t al3 = *(const uint32_t*)((aLo) + ao + 8 * STRIDE_A + 16);               \
        _Pragma("unroll") for (int p = 0; p < 6; ++p) {                                  \
            uint32_t bh0, bh1, bh2, bh3;                                                 \
            ldsm_x4(bh0, bh1, bh2, bh3, (bHiA) + p * (16 * STRIDE_B) + ks * 32);         \
            mma_f16(acc[2 * p], ah0, ah1, ah2, ah3, bh0, bh1);                           \
            mma_f16(acc[2 * p], al0, al1, al2, al3, bh0, bh1);                           \
            mma_f16(acc[2 * p + 1], ah0, ah1, ah2, ah3, bh2, bh3);                       \
            mma_f16(acc[2 * p + 1], al0, al1, al2, al3, bh2, bh3);                       \
        }                                                                                \
    }

// ============================================================
// Kernel P: W1_top^T -> fp16; W1_bot^T, W2^T -> bf16 hi/lo
// ============================================================
__global__ void __launch_bounds__(256)
weight_split_kernel(const float* __restrict__ W1, const float* __restrict__ W2) {
    int i = blockIdx.x * 256 + threadIdx.x;
    if (i >= HIDDEN * HIDDEN) return;
    int k = i / HIDDEN, n = i % HIDDEN;
    g_W1Tf16[n * HIDDEN + k] = __float2half_rn(W1[k * HIDDEN + n]);
    {
        float w = W1[(HIDDEN + k) * HIDDEN + n];
        __nv_bfloat16 hi = __float2bfloat16(w);
        g_W1bThi[n * HIDDEN + k] = hi;
        g_W1bTlo[n * HIDDEN + k] = __float2bfloat16(w - __bfloat162float(hi));
    }
    {
        float w = W2[k * HIDDEN + n];
        __nv_bfloat16 hi = __float2bfloat16(w);
        g_W2Thi[n * HIDDEN + k] = hi;
        g_W2Tlo[n * HIDDEN + k] = __float2bfloat16(w - __bfloat162float(hi));
    }
}

// ============================================================
// Kernel A: dst partial via MMA (bf16 3-term, unchanged)
// ============================================================
__global__ void __launch_bounds__(256, 2)
dst_mma_kernel(const float* __restrict__ feat, const float* __restrict__ pos,
               const int* __restrict__ dst_idx, const float* __restrict__ Win,
               const float* __restrict__ bin, const float* __restrict__ b1) {
    __shared__ __align__(16) unsigned char sAhi[64 * STRIDE_A];
    __shared__ __align__(16) unsigned char sAlo[64 * STRIDE_A];
    __shared__ __align__(16) unsigned char sBhi[HIDDEN * STRIDE_B];
    __shared__ __align__(16) unsigned char sBlo[HIDDEN * STRIDE_B];
    __shared__ float sWin[3 * HIDDEN], sBin[HIDDEN], sOmega[32], sB1[HIDDEN];

    const int tid = threadIdx.x;
    const int lane = tid & 31;
    const int w = tid >> 5;
    const int wm = w & 3, wn = w >> 2;
    const int g = lane >> 2, tg = lane & 3;
    const int s0 = blockIdx.x * 64;

    for (int i = tid; i < 3 * HIDDEN; i += 256) sWin[i] = Win[i];
    for (int i = tid; i < HIDDEN; i += 256) sBin[i] = bin[i];
    for (int i = tid; i < HIDDEN; i += 256) sB1[i] = b1[i];
    if (tid < 32) sOmega[tid] = exp2f(-(float)tid * 0.4152410118609203f);

    float f0 = 0.f, f1 = 0.f, f2 = 0.f, pp[3] = {0.f, 0.f, 0.f};
    const int m = tid & 63;
    const int cg = (tid >> 6) & 1;
    if (tid < 128) {
        int node = dst_idx[(s0 + m) * MAXDEG];
        f0 = feat[node * 3]; f1 = feat[node * 3 + 1]; f2 = feat[node * 3 + 2];
        pp[0] = pos[node * 3]; pp[1] = pos[node * 3 + 1]; pp[2] = pos[node * 3 + 2];
    }
    __syncthreads();

    float acc[12][4];
#pragma unroll
    for (int i = 0; i < 12; ++i)
#pragma unroll
        for (int j = 0; j < 4; ++j) acc[i][j] = 0.0f;

    const uint32_t aoff = (uint32_t)(wm * 16 + g) * STRIDE_A + tg * 4;
    const uint32_t bHiA = smem_u32(sBhi) + b_lane_off(wn, lane);
    const uint32_t bLoA = smem_u32(sBlo) + b_lane_off(wn, lane);

    for (int ch = 0; ch < 6; ++ch) {
        if (tid < 128) {
            const int jb = cg * 16;
#pragma unroll
            for (int j = 0; j < 16; j += 2) {
                int c0 = ch * 32 + jb + j;
                float v0 = embed_channel(c0, f0, f1, f2, pp, sWin, sBin, sOmega);
                float v1 = embed_channel(c0 + 1, f0, f1, f2, pp, sWin, sBin, sOmega);
                __nv_bfloat16 h0 = __float2bfloat16(v0);
                __nv_bfloat16 h1 = __float2bfloat16(v1);
                float l0 = v0 - __bfloat162float(h0);
                float l1 = v1 - __bfloat162float(h1);
                __nv_bfloat162 hp; hp.x = h0; hp.y = h1;
                *(uint32_t*)(sAhi + m * STRIDE_A + (jb + j) * 2) =
                    *reinterpret_cast<uint32_t*>(&hp);
                *(uint32_t*)(sAlo + m * STRIDE_A + (jb + j) * 2) = pack_bf16(l0, l1);
            }
        } else {
            const int t2 = tid - 128;
#pragma unroll
            for (int i = 0; i < 12; ++i) {
                int isLo = i >= 6;
                int id = t2 + 128 * (isLo ? (i - 6) : i);
                int n = id >> 2, seg = id & 3;
                const __nv_bfloat16* src =
                    (isLo ? g_W1bTlo : g_W1bThi) + n * HIDDEN + ch * 32 + seg * 8;
                unsigned char* dst = (isLo ? sBlo : sBhi) + n * STRIDE_B + seg * 16;
                *reinterpret_cast<uint4*>(dst) = *reinterpret_cast<const uint4*>(src);
            }
        }
        __syncthreads();
        CONSUME_CHUNK(sAhi, sAlo, bHiA, bLoA)
        __syncthreads();
    }

    const int r_hi = s0 + wm * 16 + g;
#pragma unroll
    for (int in = 0; in < 12; ++in) {
        int c = wn * 96 + in * 8 + tg * 2;
        float2 bb = *(const float2*)&sB1[c];
        float2 v0 = {acc[in][0] + bb.x, acc[in][1] + bb.y};
        float2 v1 = {acc[in][2] + bb.x, acc[in][3] + bb.y};
        *(float2*)&g_dstpart[r_hi * HIDDEN + c] = v0;
        *(float2*)&g_dstpart[(r_hi + 8) * HIDDEN + c] = v1;
    }
}

// ============================================================
// Kernel B: pipelined snp_mma — fp16 2-term, B single plane
// ============================================================
#define AB (64 * STRIDE_A)        // 4608
#define BBUF (HIDDEN * STRIDE_B)  // 15360
#define OFF_AHI 0
#define OFF_ALO (2 * AB)                 // 9216
#define OFF_BHI (4 * AB)                 // 18432 (double-buffered, hi only)
#define OFF_WIN (4 * AB + 2 * BBUF)      // 49152
#define OFF_BIN (OFF_WIN + 3 * HIDDEN * 4)
#define OFF_OMG (OFF_BIN + HIDDEN * 4)
#define OFF_DST (OFF_OMG + 128)
#define OFF_COL (OFF_DST + 2 * HIDDEN * 4)
#define SMEMB_TOTAL (OFF_COL + 4 * HIDDEN * 4)   // 56960

__device__ __forceinline__ void produce_A_f16(unsigned char* aHi, unsigned char* aLo,
                                              int ch, int m, int jb, float f0, float f1,
                                              float f2, const float* pp, const float* sWin,
                                              const float* sBin, const float* sOmega) {
#pragma unroll
    for (int j = 0; j < 16; j += 2) {
        int c0 = ch * 32 + jb + j;
        float v0 = embed_channel(c0, f0, f1, f2, pp, sWin, sBin, sOmega);
        float v1 = embed_channel(c0 + 1, f0, f1, f2, pp, sWin, sBin, sOmega);
        __half h0 = __float2half_rn(v0);
        __half h1 = __float2half_rn(v1);
        float l0 = v0 - __half2float(h0);
        float l1 = v1 - __half2float(h1);
        __half2 hp; hp.x = h0; hp.y = h1;
        *(uint32_t*)(aHi + m * STRIDE_A + (jb + j) * 2) = *reinterpret_cast<uint32_t*>(&hp);
        *(uint32_t*)(aLo + m * STRIDE_A + (jb + j) * 2) = pack_f16(l0, l1);
    }
}

__device__ __forceinline__ void copy_B_async_f16(unsigned char* bHi, int ch, int t2) {
#pragma unroll
    for (int i = 0; i < 6; ++i) {
        int id = t2 + 128 * i;   // 0..767
        int n = id >> 2, seg = id & 3;
        const __half* src = g_W1Tf16 + n * HIDDEN + ch * 32 + seg * 8;
        cp_async16(bHi + n * STRIDE_B + seg * 16, src);
    }
}

__global__ void __launch_bounds__(256, 2)
snp_mma_kernel(const float* __restrict__ feat, const float* __restrict__ pos,
               const int* __restrict__ src_idx, const float* __restrict__ Win,
               const float* __restrict__ bin) {
    extern __shared__ __align__(16) unsigned char sm[];
    float* sWin = (float*)(sm + OFF_WIN);
    float* sBin = (float*)(sm + OFF_BIN);
    float* sOmega = (float*)(sm + OFF_OMG);
    float* sDst = (float*)(sm + OFF_DST);
    float* sCol = (float*)(sm + OFF_COL);   // [4][HIDDEN]

    const int b = blockIdx.x;
    const int tid = threadIdx.x;
    const int lane = tid & 31;
    const int w = tid >> 5;
    const int wm = w & 3, wn = w >> 2;
    const int g = lane >> 2, tg = lane & 3;

    for (int i = tid; i < 3 * HIDDEN; i += 256) sWin[i] = Win[i];
    for (int i = tid; i < HIDDEN; i += 256) sBin[i] = bin[i];
    for (int i = tid; i < 2 * HIDDEN; i += 256) sDst[i] = g_dstpart[b * 2 * HIDDEN + i];
    if (tid < 32) sOmega[tid] = exp2f(-(float)tid * 0.4152410118609203f);

    float f0 = 0.f, f1 = 0.f, f2 = 0.f, pp[3] = {0.f, 0.f, 0.f};
    const int m = tid & 63;
    const int jb = ((tid >> 6) & 1) * 16;
    if (tid < 128) {
        int node = src_idx[b * 64 + m];
        f0 = feat[node * 3]; f1 = feat[node * 3 + 1]; f2 = feat[node * 3 + 2];
        pp[0] = pos[node * 3]; pp[1] = pos[node * 3 + 1]; pp[2] = pos[node * 3 + 2];
    }
    const int t2 = tid - 128;
    __syncthreads();

    float acc[12][4];
#pragma unroll
    for (int i = 0; i < 12; ++i)
#pragma unroll
        for (int j = 0; j < 4; ++j) acc[i][j] = 0.0f;

    const uint32_t aoff = (uint32_t)(wm * 16 + g) * STRIDE_A + tg * 4;
    const uint32_t smB = smem_u32(sm);
    const uint32_t bLane = b_lane_off(wn, lane);

    // ---- prologue: fill buffer 0 with chunk 0 ----
    if (tid < 128) {
        produce_A_f16(sm + OFF_AHI, sm + OFF_ALO, 0, m, jb, f0, f1, f2, pp, sWin, sBin,
                      sOmega);
    } else {
        copy_B_async_f16(sm + OFF_BHI, 0, t2);
        cp_async_commit();
        cp_async_wait0();
    }
    __syncthreads();

    // ---- pipelined main loop: produce(c+1) overlaps MMA(c) ----
    for (int c = 0; c < 6; ++c) {
        const int cur = c & 1;
        const int nxt = (c + 1) & 1;
        if (c < 5) {
            if (tid < 128) {
                produce_A_f16(sm + OFF_AHI + nxt * AB, sm + OFF_ALO + nxt * AB, c + 1, m,
                              jb, f0, f1, f2, pp, sWin, sBin, sOmega);
            } else {
                copy_B_async_f16(sm + OFF_BHI + nxt * BBUF, c + 1, t2);
                cp_async_commit();
            }
        }

        const unsigned char* aHi = sm + OFF_AHI + cur * AB;
        const unsigned char* aLo = sm + OFF_ALO + cur * AB;
        const uint32_t bHiA = smB + OFF_BHI + cur * BBUF + bLane;
        CONSUME_CHUNK_F16(aHi, aLo, bHiA)

        if (c < 5 && tid >= 128) cp_async_wait0();
        __syncthreads();
    }

    // ---- epilogue: + dstpart, GELU, column sums over this warp's 16 rows ----
    const int sn = wm >> 1;
#pragma unroll
    for (int in = 0; in < 12; ++in) {
        int c = wn * 96 + in * 8 + tg * 2;
        float2 d = *(const float2*)&sDst[sn * HIDDEN + c];
        float t0 = gelu_exact(acc[in][0] + d.x) + gelu_exact(acc[in][2] + d.x);
        float t1 = gelu_exact(acc[in][1] + d.y) + gelu_exact(acc[in][3] + d.y);
#pragma unroll
        for (int off = 4; off < 32; off <<= 1) {
            t0 += __shfl_xor_sync(0xffffffffu, t0, off);
            t1 += __shfl_xor_sync(0xffffffffu, t1, off);
        }
        if (lane < 4) {
            sCol[wm * HIDDEN + c] = t0;
            sCol[wm * HIDDEN + c + 1] = t1;
        }
    }
    __syncthreads();
    for (int i = tid; i < 2 * HIDDEN; i += 256) {
        int s = i / HIDDEN, n = i % HIDDEN;
        g_pooled[(b * 2 + s) * HIDDEN + n] =
            (sCol[s * 2 * HIDDEN + n] + sCol[(s * 2 + 1) * HIDDEN + n]) * (1.0f / 32.0f);
    }
}

// ============================================================
// Kernel C: out = g_pooled @ W2 + b2 via MMA (bf16 3-term, unchanged)
// ============================================================
__global__ void __launch_bounds__(256, 2)
out_mma_kernel(const float* __restrict__ b2, float* __restrict__ out) {
    __shared__ __align__(16) unsigned char sAhi[64 * STRIDE_A];
    __shared__ __align__(16) unsigned char sAlo[64 * STRIDE_A];
    __shared__ __align__(16) unsigned char sBhi[HIDDEN * STRIDE_B];
    __shared__ __align__(16) unsigned char sBlo[HIDDEN * STRIDE_B];
    __shared__ float sB2[HIDDEN];

    const int tid = threadIdx.x;
    const int lane = tid & 31;
    const int w = tid >> 5;
    const int wm = w & 3, wn = w >> 2;
    const int g = lane >> 2, tg = lane & 3;
    const int s0 = blockIdx.x * 64;

    for (int i = tid; i < HIDDEN; i += 256) sB2[i] = b2[i];

    const int m = tid & 63;
    const int cg = (tid >> 6) & 1;

    float acc[12][4];
#pragma unroll
    for (int i = 0; i < 12; ++i)
#pragma unroll
        for (int j = 0; j < 4; ++j) acc[i][j] = 0.0f;

    const uint32_t aoff = (uint32_t)(wm * 16 + g) * STRIDE_A + tg * 4;
    const uint32_t bHiA = smem_u32(sBhi) + b_lane_off(wn, lane);
    const uint32_t bLoA = smem_u32(sBlo) + b_lane_off(wn, lane);

    for (int ch = 0; ch < 6; ++ch) {
        if (tid < 128) {
            const int jb = cg * 16;
            const float* arow = g_pooled + (s0 + m) * HIDDEN + ch * 32 + jb;
#pragma unroll
            for (int j = 0; j < 16; j += 2) {
                float2 v = *(const float2*)&arow[j];
                __nv_bfloat16 h0 = __float2bfloat16(v.x);
                __nv_bfloat16 h1 = __float2bfloat16(v.y);
                float l0 = v.x - __bfloat162float(h0);
                float l1 = v.y - __bfloat162float(h1);
                __nv_bfloat162 hp; hp.x = h0; hp.y = h1;
                *(uint32_t*)(sAhi + m * STRIDE_A + (jb + j) * 2) =
                    *reinterpret_cast<uint32_t*>(&hp);
                *(uint32_t*)(sAlo + m * STRIDE_A + (jb + j) * 2) = pack_bf16(l0, l1);
            }
        } else {
            const int t2 = tid - 128;
#pragma unroll
            for (int i = 0; i < 12; ++i) {
                int isLo = i >= 6;
                int id = t2 + 128 * (isLo ? (i - 6) : i);
                int n = id >> 2, seg = id & 3;
                const __nv_bfloat16* src =
                    (isLo ? g_W2Tlo : g_W2Thi) + n * HIDDEN + ch * 32 + seg * 8;
                unsigned char* dst = (isLo ? sBlo : sBhi) + n * STRIDE_B + seg * 16;
                *reinterpret_cast<uint4*>(dst) = *reinterpret_cast<const uint4*>(src);
            }
        }
        __syncthreads();
        CONSUME_CHUNK(sAhi, sAlo, bHiA, bLoA)
        __syncthreads();
    }

    const int r_hi = s0 + wm * 16 + g;
#pragma unroll
    for (int in = 0; in < 12; ++in) {
        int c = wn * 96 + in * 8 + tg * 2;
        float2 bb = *(const float2*)&sB2[c];
        float2 v0 = {acc[in][0] + bb.x, acc[in][1] + bb.y};
        float2 v1 = {acc[in][2] + bb.x, acc[in][3] + bb.y};
        *(float2*)&out[r_hi * HIDDEN + c] = v0;
        *(float2*)&out[(r_hi + 8) * HIDDEN + c] = v1;
    }
}

// ============================================================
extern "C" void kernel_launch(void* const* d_in, const int* in_sizes, int n_in,
                              void* d_out, int out_size) {
    const float* feat = (const float*)d_in[0];
    const float* pos = (const float*)d_in[1];
    const int* src_idx = (const int*)d_in[2];
    const int* dst_idx = (const int*)d_in[3];
    const float* Win = (const float*)d_in[4];
    const float* bin = (const float*)d_in[5];
    const float* W1 = (const float*)d_in[6];
    const float* b1 = (const float*)d_in[7];
    const float* W2 = (const float*)d_in[8];
    const float* b2 = (const float*)d_in[9];
    float* out = (float*)d_out;

    const int E = in_sizes[2];
    const int S = E / MAXDEG;   // 8192

    static int smem_set = 0;
    if (!smem_set) {
        cudaFuncSetAttribute(snp_mma_kernel, cudaFuncAttributeMaxDynamicSharedMemorySize,
                             SMEMB_TOTAL);
        smem_set = 1;
    }

    weight_split_kernel<<<(HIDDEN * HIDDEN + 255) / 256, 256>>>(W1, W2);
    dst_mma_kernel<<<S / 64, 256>>>(feat, pos, dst_idx, Win, bin, b1);
    snp_mma_kernel<<<S / 2, 256, SMEMB_TOTAL>>>(feat, pos, src_idx, Win, bin);
    out_mma_kernel<<<S / 64, 256>>>(b2, out);
}

// round 10
// speedup vs baseline: 3.6587x; 1.2914x over previous
#include <cuda_runtime.h>
#include <cuda_bf16.h>
#include <cuda_fp16.h>
#include <cstdint>

#define HIDDEN 192
#define MAXDEG 32
#define MAX_S 8192

// scratch (device globals: allocation-free). 16B-aligned for vector ld/st + cp.async.
__device__ __align__(16) float g_dstpart[MAX_S * HIDDEN];         // b1 + x_dst @ W1_bot
__device__ __align__(16) float g_pooled[MAX_S * HIDDEN];          // mean(gelu(...))
__device__ __align__(16) __half g_W1Tf16[HIDDEN * HIDDEN];        // W1_top^T fp16 [n][k]
__device__ __align__(16) __nv_bfloat16 g_W1bThi[HIDDEN * HIDDEN]; // W1_bot^T hi
__device__ __align__(16) __nv_bfloat16 g_W1bTlo[HIDDEN * HIDDEN]; // W1_bot^T lo
__device__ __align__(16) __nv_bfloat16 g_W2Thi[HIDDEN * HIDDEN];  // W2^T hi
__device__ __align__(16) __nv_bfloat16 g_W2Tlo[HIDDEN * HIDDEN];  // W2^T lo

// ---------------- helpers ----------------
__device__ __forceinline__ float sin_poly(float x) {
    float x2 = x * x;
    float p = -1.98412698e-4f;
    p = fmaf(p, x2, 8.33333333e-3f);
    p = fmaf(p, x2, -1.66666667e-1f);
    return fmaf(x * x2, p, x);
}
__device__ __forceinline__ float cos_poly(float x) {
    float x2 = x * x;
    float p = 2.48015873e-5f;
    p = fmaf(p, x2, -1.38888889e-3f);
    p = fmaf(p, x2, 4.16666667e-2f);
    p = fmaf(p, x2, -0.5f);
    return fmaf(p, x2, 1.0f);
}
__device__ __forceinline__ float gelu_exact(float x) {
    return 0.5f * x * (1.0f + erff(x * 0.7071067811865476f));
}
__device__ __forceinline__ float embed_channel(int c, float f0, float f1, float f2,
                                               const float* pp, const float* sWin,
                                               const float* sBin, const float* sOmega) {
    float v = sBin[c];
    v = fmaf(f0, sWin[c], v);
    v = fmaf(f1, sWin[HIDDEN + c], v);
    v = fmaf(f2, sWin[2 * HIDDEN + c], v);
    int axis = c >> 6;
    int j = c & 63;
    float ang = pp[axis] * sOmega[j & 31];
    float e = (j < 32) ? sin_poly(ang) : cos_poly(ang);
    return v + e;
}
__device__ __forceinline__ void mma_bf16(float* c, uint32_t a0, uint32_t a1, uint32_t a2,
                                         uint32_t a3, uint32_t b0, uint32_t b1) {
    asm volatile(
        "mma.sync.aligned.m16n8k16.row.col.f32.bf16.bf16.f32 "
        "{%0,%1,%2,%3}, {%4,%5,%6,%7}, {%8,%9}, {%0,%1,%2,%3};"
        : "+f"(c[0]), "+f"(c[1]), "+f"(c[2]), "+f"(c[3])
        : "r"(a0), "r"(a1), "r"(a2), "r"(a3), "r"(b0), "r"(b1));
}
__device__ __forceinline__ void mma_f16(float* c, uint32_t a0, uint32_t a1, uint32_t a2,
                                        uint32_t a3, uint32_t b0, uint32_t b1) {
    asm volatile(
        "mma.sync.aligned.m16n8k16.row.col.f32.f16.f16.f32 "
        "{%0,%1,%2,%3}, {%4,%5,%6,%7}, {%8,%9}, {%0,%1,%2,%3};"
        : "+f"(c[0]), "+f"(c[1]), "+f"(c[2]), "+f"(c[3])
        : "r"(a0), "r"(a1), "r"(a2), "r"(a3), "r"(b0), "r"(b1));
}
__device__ __forceinline__ void ldsm_x4(uint32_t& r0, uint32_t& r1, uint32_t& r2,
                                        uint32_t& r3, uint32_t addr) {
    asm volatile("ldmatrix.sync.aligned.m8n8.x4.shared.b16 {%0,%1,%2,%3}, [%4];"
                 : "=r"(r0), "=r"(r1), "=r"(r2), "=r"(r3) : "r"(addr));
}
__device__ __forceinline__ uint32_t pack_bf16(float v0, float v1) {
    __nv_bfloat162 t;
    t.x = __float2bfloat16(v0);
    t.y = __float2bfloat16(v1);
    return *reinterpret_cast<uint32_t*>(&t);
}
__device__ __forceinline__ uint32_t pack_f16(float v0, float v1) {
    __half2 t;
    t.x = __float2half_rn(v0);
    t.y = __float2half_rn(v1);
    return *reinterpret_cast<uint32_t*>(&t);
}
__device__ __forceinline__ uint32_t smem_u32(const void* p) {
    uint32_t a;
    asm("{ .reg .u64 t; cvta.to.shared.u64 t, %1; cvt.u32.u64 %0, t; }" : "=r"(a) : "l"(p));
    return a;
}
__device__ __forceinline__ void cp_async16(void* dst_smem, const void* src) {
    uint32_t d = smem_u32(dst_smem);
    asm volatile("cp.async.cg.shared.global [%0], [%1], 16;" :: "r"(d), "l"(src) : "memory");
}
__device__ __forceinline__ void cp_async_commit() {
    asm volatile("cp.async.commit_group;" ::: "memory");
}
__device__ __forceinline__ void cp_async_wait0() {
    asm volatile("cp.async.wait_group 0;" ::: "memory");
}

#define STRIDE_A 72  // 32 x b16 (64B) + 8B pad
#define STRIDE_B 80  // 32 x b16 (64B) + 16B pad; LDSM-conflict-free

// B-fragment lane offset for ldmatrix.x4 (pair p covers atoms 2p, 2p+1)
__device__ __forceinline__ uint32_t b_lane_off(int wn, int lane) {
    return (uint32_t)(wn * 96 + ((lane >> 4) & 1) * 8 + (lane & 7)) * STRIDE_B +
           ((lane >> 3) & 1) * 16;
}

// bf16 3-term consume (dst/out kernels)
#define CONSUME_CHUNK(aHi, aLo, bHiA, bLoA)                                              \
    _Pragma("unroll") for (int ks = 0; ks < 2; ++ks) {                                   \
        const uint32_t ao = aoff + ks * 32;                                              \
        uint32_t ah0 = *(const uint32_t*)((aHi) + ao);                                   \
        uint32_t ah1 = *(const uint32_t*)((aHi) + ao + 8 * STRIDE_A);                    \
        uint32_t ah2 = *(const uint32_t*)((aHi) + ao + 16);                              \
        uint32_t ah3 = *(const uint32_t*)((aHi) + ao + 8 * STRIDE_A + 16);               \
        uint32_t al0 = *(const uint32_t*)((aLo) + ao);                                   \
        uint32_t al1 = *(const uint32_t*)((aLo) + ao + 8 * STRIDE_A);                    \
        uint32_t al2 = *(const uint32_t*)((aLo) + ao + 16);                              \
        uint32_t al3 = *(const uint32_t*)((aLo) + ao + 8 * STRIDE_A + 16);               \
        _Pragma("unroll") for (int p = 0; p < 6; ++p) {                                  \
            uint32_t bh0, bh1, bh2, bh3, bl0, bl1, bl2, bl3;                             \
            ldsm_x4(bh0, bh1, bh2, bh3, (bHiA) + p * (16 * STRIDE_B) + ks * 32);         \
            ldsm_x4(bl0, bl1, bl2, bl3, (bLoA) + p * (16 * STRIDE_B) + ks * 32);         \
            mma_bf16(acc[2 * p], ah0, ah1, ah2, ah3, bh0, bh1);                          \
            mma_bf16(acc[2 * p], al0, al1, al2, al3, bh0, bh1);                          \
            mma_bf16(acc[2 * p], ah0, ah1, ah2, ah3, bl0, bl1);                          \
            mma_bf16(acc[2 * p + 1], ah0, ah1, ah2, ah3, bh2, bh3);                      \
            mma_bf16(acc[2 * p + 1], al0, al1, al2, al3, bh2, bh3);                      \
            mma_bf16(acc[2 * p + 1], ah0, ah1, ah2, ah3, bl2, bl3);                      \
        }                                                                                \
    }

// fp16 single-term consume (snp): pure fp16 A x B
#define CONSUME_CHUNK_F16_1(aHi, bHiA)                                                   \
    _Pragma("unroll") for (int ks = 0; ks < 2; ++ks) {                                   \
        const uint32_t ao = aoff + ks * 32;                                              \
        uint32_t ah0 = *(const uint32_t*)((aHi) + ao);                                   \
        uint32_t ah1 = *(const uint32_t*)((aHi) + ao + 8 * STRIDE_A);                    \
        uint32_t ah2 = *(const uint32_t*)((aHi) + ao + 16);                              \
        uint32_t ah3 = *(const uint32_t*)((aHi) + ao + 8 * STRIDE_A + 16);               \
        _Pragma("unroll") for (int p = 0; p < 6; ++p) {                                  \
            uint32_t bh0, bh1, bh2, bh3;                                                 \
            ldsm_x4(bh0, bh1, bh2, bh3, (bHiA) + p * (16 * STRIDE_B) + ks * 32);         \
            mma_f16(acc[2 * p], ah0, ah1, ah2, ah3, bh0, bh1);                           \
            mma_f16(acc[2 * p + 1], ah0, ah1, ah2, ah3, bh2, bh3);                       \
        }                                                                                \
    }

// ============================================================
// Kernel P: W1_top^T -> fp16; W1_bot^T, W2^T -> bf16 hi/lo
// ============================================================
__global__ void __launch_bounds__(256)
weight_split_kernel(const float* __restrict__ W1, const float* __restrict__ W2) {
    int i = blockIdx.x * 256 + threadIdx.x;
    if (i >= HIDDEN * HIDDEN) return;
    int k = i / HIDDEN, n = i % HIDDEN;
    g_W1Tf16[n * HIDDEN + k] = __float2half_rn(W1[k * HIDDEN + n]);
    {
        float w = W1[(HIDDEN + k) * HIDDEN + n];
        __nv_bfloat16 hi = __float2bfloat16(w);
        g_W1bThi[n * HIDDEN + k] = hi;
        g_W1bTlo[n * HIDDEN + k] = __float2bfloat16(w - __bfloat162float(hi));
    }
    {
        float w = W2[k * HIDDEN + n];
        __nv_bfloat16 hi = __float2bfloat16(w);
        g_W2Thi[n * HIDDEN + k] = hi;
        g_W2Tlo[n * HIDDEN + k] = __float2bfloat16(w - __bfloat162float(hi));
    }
}

// ============================================================
// Kernel A: dst partial via MMA (bf16 3-term, unchanged)
// ============================================================
__global__ void __launch_bounds__(256, 2)
dst_mma_kernel(const float* __restrict__ feat, const float* __restrict__ pos,
               const int* __restrict__ dst_idx, const float* __restrict__ Win,
               const float* __restrict__ bin, const float* __restrict__ b1) {
    __shared__ __align__(16) unsigned char sAhi[64 * STRIDE_A];
    __shared__ __align__(16) unsigned char sAlo[64 * STRIDE_A];
    __shared__ __align__(16) unsigned char sBhi[HIDDEN * STRIDE_B];
    __shared__ __align__(16) unsigned char sBlo[HIDDEN * STRIDE_B];
    __shared__ float sWin[3 * HIDDEN], sBin[HIDDEN], sOmega[32], sB1[HIDDEN];

    const int tid = threadIdx.x;
    const int lane = tid & 31;
    const int w = tid >> 5;
    const int wm = w & 3, wn = w >> 2;
    const int g = lane >> 2, tg = lane & 3;
    const int s0 = blockIdx.x * 64;

    for (int i = tid; i < 3 * HIDDEN; i += 256) sWin[i] = Win[i];
    for (int i = tid; i < HIDDEN; i += 256) sBin[i] = bin[i];
    for (int i = tid; i < HIDDEN; i += 256) sB1[i] = b1[i];
    if (tid < 32) sOmega[tid] = exp2f(-(float)tid * 0.4152410118609203f);

    float f0 = 0.f, f1 = 0.f, f2 = 0.f, pp[3] = {0.f, 0.f, 0.f};
    const int m = tid & 63;
    const int cg = (tid >> 6) & 1;
    if (tid < 128) {
        int node = dst_idx[(s0 + m) * MAXDEG];
        f0 = feat[node * 3]; f1 = feat[node * 3 + 1]; f2 = feat[node * 3 + 2];
        pp[0] = pos[node * 3]; pp[1] = pos[node * 3 + 1]; pp[2] = pos[node * 3 + 2];
    }
    __syncthreads();

    float acc[12][4];
#pragma unroll
    for (int i = 0; i < 12; ++i)
#pragma unroll
        for (int j = 0; j < 4; ++j) acc[i][j] = 0.0f;

    const uint32_t aoff = (uint32_t)(wm * 16 + g) * STRIDE_A + tg * 4;
    const uint32_t bHiA = smem_u32(sBhi) + b_lane_off(wn, lane);
    const uint32_t bLoA = smem_u32(sBlo) + b_lane_off(wn, lane);

    for (int ch = 0; ch < 6; ++ch) {
        if (tid < 128) {
            const int jb = cg * 16;
#pragma unroll
            for (int j = 0; j < 16; j += 2) {
                int c0 = ch * 32 + jb + j;
                float v0 = embed_channel(c0, f0, f1, f2, pp, sWin, sBin, sOmega);
                float v1 = embed_channel(c0 + 1, f0, f1, f2, pp, sWin, sBin, sOmega);
                __nv_bfloat16 h0 = __float2bfloat16(v0);
                __nv_bfloat16 h1 = __float2bfloat16(v1);
                float l0 = v0 - __bfloat162float(h0);
                float l1 = v1 - __bfloat162float(h1);
                __nv_bfloat162 hp; hp.x = h0; hp.y = h1;
                *(uint32_t*)(sAhi + m * STRIDE_A + (jb + j) * 2) =
                    *reinterpret_cast<uint32_t*>(&hp);
                *(uint32_t*)(sAlo + m * STRIDE_A + (jb + j) * 2) = pack_bf16(l0, l1);
            }
        } else {
            const int t2 = tid - 128;
#pragma unroll
            for (int i = 0; i < 12; ++i) {
                int isLo = i >= 6;
                int id = t2 + 128 * (isLo ? (i - 6) : i);
                int n = id >> 2, seg = id & 3;
                const __nv_bfloat16* src =
                    (isLo ? g_W1bTlo : g_W1bThi) + n * HIDDEN + ch * 32 + seg * 8;
                unsigned char* dst = (isLo ? sBlo : sBhi) + n * STRIDE_B + seg * 16;
                *reinterpret_cast<uint4*>(dst) = *reinterpret_cast<const uint4*>(src);
            }
        }
        __syncthreads();
        CONSUME_CHUNK(sAhi, sAlo, bHiA, bLoA)
        __syncthreads();
    }

    const int r_hi = s0 + wm * 16 + g;
#pragma unroll
    for (int in = 0; in < 12; ++in) {
        int c = wn * 96 + in * 8 + tg * 2;
        float2 bb = *(const float2*)&sB1[c];
        float2 v0 = {acc[in][0] + bb.x, acc[in][1] + bb.y};
        float2 v1 = {acc[in][2] + bb.x, acc[in][3] + bb.y};
        *(float2*)&g_dstpart[r_hi * HIDDEN + c] = v0;
        *(float2*)&g_dstpart[(r_hi + 8) * HIDDEN + c] = v1;
    }
}

// ============================================================
// Kernel B: pipelined snp_mma — pure fp16 single-term, all-thread
// producers, occ 3. Dynamic smem ~47.7KB.
// ============================================================
#define AB (64 * STRIDE_A)        // 4608
#define BBUF (HIDDEN * STRIDE_B)  // 15360
#define OFF_AHI 0                        // 2 bufs: 9216
#define OFF_BHI (2 * AB)                 // 9216, 2 bufs: 30720
#define OFF_WIN (2 * AB + 2 * BBUF)      // 39936
#define OFF_BIN (OFF_WIN + 3 * HIDDEN * 4)
#define OFF_OMG (OFF_BIN + HIDDEN * 4)
#define OFF_DST (OFF_OMG + 128)
#define OFF_COL (OFF_DST + 2 * HIDDEN * 4)
#define SMEMB_TOTAL (OFF_COL + 4 * HIDDEN * 4)   // 47744

// all 256 threads: 8 embedding channels each (row m, channels [jb, jb+8))
__device__ __forceinline__ void produce_A8(unsigned char* aHi, int ch, int m, int jb,
                                           float f0, float f1, float f2, const float* pp,
                                           const float* sWin, const float* sBin,
                                           const float* sOmega) {
#pragma unroll
    for (int j = 0; j < 8; j += 2) {
        int c0 = ch * 32 + jb + j;
        float v0 = embed_channel(c0, f0, f1, f2, pp, sWin, sBin, sOmega);
        float v1 = embed_channel(c0 + 1, f0, f1, f2, pp, sWin, sBin, sOmega);
        *(uint32_t*)(aHi + m * STRIDE_A + (jb + j) * 2) = pack_f16(v0, v1);
    }
}

// all 256 threads: 3 x 16B B segments each (768 total)
__device__ __forceinline__ void copy_B3(unsigned char* bHi, int ch, int tid) {
#pragma unroll
    for (int i = 0; i < 3; ++i) {
        int id = tid + 256 * i;   // 0..767
        int n = id >> 2, seg = id & 3;
        cp_async16(bHi + n * STRIDE_B + seg * 16,
                   g_W1Tf16 + n * HIDDEN + ch * 32 + seg * 8);
    }
}

__global__ void __launch_bounds__(256, 3)
snp_mma_kernel(const float* __restrict__ feat, const float* __restrict__ pos,
               const int* __restrict__ src_idx, const float* __restrict__ Win,
               const float* __restrict__ bin) {
    extern __shared__ __align__(16) unsigned char sm[];
    float* sWin = (float*)(sm + OFF_WIN);
    float* sBin = (float*)(sm + OFF_BIN);
    float* sOmega = (float*)(sm + OFF_OMG);
    float* sDst = (float*)(sm + OFF_DST);
    float* sCol = (float*)(sm + OFF_COL);   // [4][HIDDEN]

    const int b = blockIdx.x;
    const int tid = threadIdx.x;
    const int lane = tid & 31;
    const int w = tid >> 5;
    const int wm = w & 3, wn = w >> 2;
    const int g = lane >> 2, tg = lane & 3;

    for (int i = tid; i < 3 * HIDDEN; i += 256) sWin[i] = Win[i];
    for (int i = tid; i < HIDDEN; i += 256) sBin[i] = bin[i];
    for (int i = tid; i < 2 * HIDDEN; i += 256) sDst[i] = g_dstpart[b * 2 * HIDDEN + i];
    if (tid < 32) sOmega[tid] = exp2f(-(float)tid * 0.4152410118609203f);

    // every thread owns row m = tid & 63, channel quarter jb = (tid>>6)*8
    const int m = tid & 63;
    const int jb = (tid >> 6) * 8;
    int node = src_idx[b * 64 + m];
    float f0 = feat[node * 3], f1 = feat[node * 3 + 1], f2 = feat[node * 3 + 2];
    float pp[3] = {pos[node * 3], pos[node * 3 + 1], pos[node * 3 + 2]};
    __syncthreads();   // consts ready

    float acc[12][4];
#pragma unroll
    for (int i = 0; i < 12; ++i)
#pragma unroll
        for (int j = 0; j < 4; ++j) acc[i][j] = 0.0f;

    const uint32_t aoff = (uint32_t)(wm * 16 + g) * STRIDE_A + tg * 4;
    const uint32_t smB = smem_u32(sm);
    const uint32_t bLane = b_lane_off(wn, lane);

    // ---- prologue: fill buffer 0 with chunk 0 ----
    produce_A8(sm + OFF_AHI, 0, m, jb, f0, f1, f2, pp, sWin, sBin, sOmega);
    copy_B3(sm + OFF_BHI, 0, tid);
    cp_async_commit();
    cp_async_wait0();
    __syncthreads();

    // ---- pipelined main loop: produce(c+1) overlaps MMA(c) ----
    for (int c = 0; c < 6; ++c) {
        const int cur = c & 1;
        const int nxt = (c + 1) & 1;
        if (c < 5) {
            produce_A8(sm + OFF_AHI + nxt * AB, c + 1, m, jb, f0, f1, f2, pp, sWin, sBin,
                       sOmega);
            copy_B3(sm + OFF_BHI + nxt * BBUF, c + 1, tid);
            cp_async_commit();
        }

        const unsigned char* aHi = sm + OFF_AHI + cur * AB;
        const uint32_t bHiA = smB + OFF_BHI + cur * BBUF + bLane;
        CONSUME_CHUNK_F16_1(aHi, bHiA)

        if (c < 5) cp_async_wait0();
        __syncthreads();
    }

    // ---- epilogue: + dstpart, GELU, column sums over this warp's 16 rows ----
    const int sn = wm >> 1;
#pragma unroll
    for (int in = 0; in < 12; ++in) {
        int c = wn * 96 + in * 8 + tg * 2;
        float2 d = *(const float2*)&sDst[sn * HIDDEN + c];
        float t0 = gelu_exact(acc[in][0] + d.x) + gelu_exact(acc[in][2] + d.x);
        float t1 = gelu_exact(acc[in][1] + d.y) + gelu_exact(acc[in][3] + d.y);
#pragma unroll
        for (int off = 4; off < 32; off <<= 1) {
            t0 += __shfl_xor_sync(0xffffffffu, t0, off);
            t1 += __shfl_xor_sync(0xffffffffu, t1, off);
        }
        if (lane < 4) {
            sCol[wm * HIDDEN + c] = t0;
            sCol[wm * HIDDEN + c + 1] = t1;
        }
    }
    __syncthreads();
    for (int i = tid; i < 2 * HIDDEN; i += 256) {
        int s = i / HIDDEN, n = i % HIDDEN;
        g_pooled[(b * 2 + s) * HIDDEN + n] =
            (sCol[s * 2 * HIDDEN + n] + sCol[(s * 2 + 1) * HIDDEN + n]) * (1.0f / 32.0f);
    }
}

// ============================================================
// Kernel C: out = g_pooled @ W2 + b2 via MMA (bf16 3-term, unchanged)
// ============================================================
__global__ void __launch_bounds__(256, 2)
out_mma_kernel(const float* __restrict__ b2, float* __restrict__ out) {
    __shared__ __align__(16) unsigned char sAhi[64 * STRIDE_A];
    __shared__ __align__(16) unsigned char sAlo[64 * STRIDE_A];
    __shared__ __align__(16) unsigned char sBhi[HIDDEN * STRIDE_B];
    __shared__ __align__(16) unsigned char sBlo[HIDDEN * STRIDE_B];
    __shared__ float sB2[HIDDEN];

    const int tid = threadIdx.x;
    const int lane = tid & 31;
    const int w = tid >> 5;
    const int wm = w & 3, wn = w >> 2;
    const int g = lane >> 2, tg = lane & 3;
    const int s0 = blockIdx.x * 64;

    for (int i = tid; i < HIDDEN; i += 256) sB2[i] = b2[i];

    const int m = tid & 63;
    const int cg = (tid >> 6) & 1;

    float acc[12][4];
#pragma unroll
    for (int i = 0; i < 12; ++i)
#pragma unroll
        for (int j = 0; j < 4; ++j) acc[i][j] = 0.0f;

    const uint32_t aoff = (uint32_t)(wm * 16 + g) * STRIDE_A + tg * 4;
    const uint32_t bHiA = smem_u32(sBhi) + b_lane_off(wn, lane);
    const uint32_t bLoA = smem_u32(sBlo) + b_lane_off(wn, lane);

    for (int ch = 0; ch < 6; ++ch) {
        if (tid < 128) {
            const int jb = cg * 16;
            const float* arow = g_pooled + (s0 + m) * HIDDEN + ch * 32 + jb;
#pragma unroll
            for (int j = 0; j < 16; j += 2) {
                float2 v = *(const float2*)&arow[j];
                __nv_bfloat16 h0 = __float2bfloat16(v.x);
                __nv_bfloat16 h1 = __float2bfloat16(v.y);
                float l0 = v.x - __bfloat162float(h0);
                float l1 = v.y - __bfloat162float(h1);
                __nv_bfloat162 hp; hp.x = h0; hp.y = h1;
                *(uint32_t*)(sAhi + m * STRIDE_A + (jb + j) * 2) =
                    *reinterpret_cast<uint32_t*>(&hp);
                *(uint32_t*)(sAlo + m * STRIDE_A + (jb + j) * 2) = pack_bf16(l0, l1);
            }
        } else {
            const int t2 = tid - 128;
#pragma unroll
            for (int i = 0; i < 12; ++i) {
                int isLo = i >= 6;
                int id = t2 + 128 * (isLo ? (i - 6) : i);
                int n = id >> 2, seg = id & 3;
                const __nv_bfloat16* src =
                    (isLo ? g_W2Tlo : g_W2Thi) + n * HIDDEN + ch * 32 + seg * 8;
                unsigned char* dst = (isLo ? sBlo : sBhi) + n * STRIDE_B + seg * 16;
                *reinterpret_cast<uint4*>(dst) = *reinterpret_cast<const uint4*>(src);
            }
        }
        __syncthreads();
        CONSUME_CHUNK(sAhi, sAlo, bHiA, bLoA)
        __syncthreads();
    }

    const int r_hi = s0 + wm * 16 + g;
#pragma unroll
    for (int in = 0; in < 12; ++in) {
        int c = wn * 96 + in * 8 + tg * 2;
        float2 bb = *(const float2*)&sB2[c];
        float2 v0 = {acc[in][0] + bb.x, acc[in][1] + bb.y};
        float2 v1 = {acc[in][2] + bb.x, acc[in][3] + bb.y};
        *(float2*)&out[r_hi * HIDDEN + c] = v0;
        *(float2*)&out[(r_hi + 8) * HIDDEN + c] = v1;
    }
}

// ============================================================
extern "C" void kernel_launch(void* const* d_in, const int* in_sizes, int n_in,
                              void* d_out, int out_size) {
    const float* feat = (const float*)d_in[0];
    const float* pos = (const float*)d_in[1];
    const int* src_idx = (const int*)d_in[2];
    const int* dst_idx = (const int*)d_in[3];
    const float* Win = (const float*)d_in[4];
    const float* bin = (const float*)d_in[5];
    const float* W1 = (const float*)d_in[6];
    const float* b1 = (const float*)d_in[7];
    const float* W2 = (const float*)d_in[8];
    const float* b2 = (const float*)d_in[9];
    float* out = (float*)d_out;

    const int E = in_sizes[2];
    const int S = E / MAXDEG;   // 8192

    static int smem_set = 0;
    if (!smem_set) {
        cudaFuncSetAttribute(snp_mma_kernel, cudaFuncAttributeMaxDynamicSharedMemorySize,
                             SMEMB_TOTAL);
        smem_set = 1;
    }

    weight_split_kernel<<<(HIDDEN * HIDDEN + 255) / 256, 256>>>(W1, W2);
    dst_mma_kernel<<<S / 64, 256>>>(feat, pos, dst_idx, Win, bin, b1);
    snp_mma_kernel<<<S / 2, 256, SMEMB_TOTAL>>>(feat, pos, src_idx, Win, bin);
    out_mma_kernel<<<S / 64, 256>>>(b2, out);
}